// round 2
// baseline (speedup 1.0000x reference)
#include <cuda_runtime.h>
#include <math.h>

#define Bsz   8
#define Lseq  2048
#define Hdim  512
#define Nst   64
#define NROW  (Bsz*Lseq)          // 16384
#define BLH   (Bsz*Lseq*Hdim)     // 8388608
#define HH    (Hdim*Hdim)
#define HN    (Hdim*Nst)

// ----------------- device scratch (no allocations allowed) ------------------
__device__ float  g_x [BLH];
__device__ float  g_h [BLH];
__device__ float  g_ht[BLH];
__device__ float  g_yt[BLH];
__device__ float  g_v [BLH];
__device__ float  g_z1[BLH];
__device__ float2 g_ar[Hdim*Lseq];        // at_roots (H, 2048)
__device__ float2 g_Kd[Hdim*2049];        // rfft4096(K) bins 0..2048
__device__ float4 g_pk01[HN];             // (w00re,w00im,w01re,w01im)
__device__ float4 g_pk23[HN];             // (w10re,w10im,w11re,w11im)
__device__ float2 g_plam[HN];             // clamped Lambda
__device__ float  g_2step[Hdim];          // 2/step
__device__ float2 g_twA[1024];            // exp(-2*pi*i*j/2048)
__device__ float2 g_twB[2048];            // exp(-pi*i*k/2048)

// ----------------- helpers --------------------------------------------------
__device__ __forceinline__ float2 cadd(float2 a, float2 b){ return make_float2(a.x+b.x, a.y+b.y); }
__device__ __forceinline__ float2 csub(float2 a, float2 b){ return make_float2(a.x-b.x, a.y-b.y); }
__device__ __forceinline__ float2 cmul(float2 a, float2 b){ return make_float2(a.x*b.x-a.y*b.y, a.x*b.y+a.y*b.x); }
__device__ __forceinline__ float frcp_fast(float x){ float y; asm("rcp.approx.f32 %0, %1;" : "=f"(y) : "f"(x)); return y; }
__device__ __forceinline__ float gelu_f(float x){
  float x3 = x*x*x;
  float t  = tanhf(0.7978845608028654f*(x + 0.044715f*x3));
  return 0.5f*x*(1.0f + t);
}
__device__ __forceinline__ float sigm_f(float x){ return 1.0f/(1.0f + __expf(-x)); }

// ----------------- twiddle init ---------------------------------------------
__global__ void init_tw_kernel(){
  int i = blockIdx.x*256 + threadIdx.x;
  if (i < 1024){
    float a = (float)(6.283185307179586/2048.0) * (float)i;
    float s, c; sincosf(a, &s, &c);
    g_twA[i] = make_float2(c, -s);
  }
  if (i < 2048){
    float a = (float)(3.141592653589793/2048.0) * (float)i;
    float s, c; sincosf(a, &s, &c);
    g_twB[i] = make_float2(c, -s);
  }
}

// ----------------- layernorm: g_x -> g_h ------------------------------------
__global__ __launch_bounds__(256) void ln_kernel(const float* __restrict__ sc,
                                                 const float* __restrict__ bi){
  int warp = threadIdx.x >> 5, lane = threadIdx.x & 31;
  size_t row = (size_t)blockIdx.x*8 + warp;
  const float4* xr = (const float4*)(g_x + row*Hdim);
  float4 v[4];
  float s = 0.f, s2 = 0.f;
  #pragma unroll
  for (int i = 0; i < 4; i++){
    float4 t = xr[lane + 32*i];
    v[i] = t;
    s  += t.x + t.y + t.z + t.w;
    s2 += t.x*t.x + t.y*t.y + t.z*t.z + t.w*t.w;
  }
  #pragma unroll
  for (int o = 16; o; o >>= 1){
    s  += __shfl_xor_sync(0xffffffffu, s,  o);
    s2 += __shfl_xor_sync(0xffffffffu, s2, o);
  }
  float mean = s*(1.f/Hdim);
  float var  = s2*(1.f/Hdim) - mean*mean;
  float inv  = rsqrtf(var + 1e-6f);
  float4* orow = (float4*)(g_h + row*Hdim);
  const float4* s4 = (const float4*)sc;
  const float4* b4 = (const float4*)bi;
  #pragma unroll
  for (int i = 0; i < 4; i++){
    int ci = lane + 32*i;
    float4 sv = s4[ci], bv = b4[ci], t = v[i], o;
    o.x = (t.x-mean)*inv*sv.x + bv.x;
    o.y = (t.y-mean)*inv*sv.y + bv.y;
    o.z = (t.z-mean)*inv*sv.z + bv.z;
    o.w = (t.w-mean)*inv*sv.w + bv.w;
    orow[ci] = o;
  }
}

// ----------------- transposes -----------------------------------------------
// g_h (B,L,H) -> g_ht (B,H,L)
__global__ void transpose_fwd_kernel(){
  __shared__ float tile[32][33];
  int b  = blockIdx.z;
  int h0 = blockIdx.x*32;
  int l0 = blockIdx.y*32;
  int tx = threadIdx.x, ty = threadIdx.y;
  const float* in = g_h + (size_t)b*Lseq*Hdim;
  float* out = g_ht + (size_t)b*Hdim*Lseq;
  #pragma unroll
  for (int j = 0; j < 32; j += 8)
    tile[ty+j][tx] = in[(size_t)(l0+ty+j)*Hdim + h0 + tx];
  __syncthreads();
  #pragma unroll
  for (int j = 0; j < 32; j += 8)
    out[(size_t)(h0+ty+j)*Lseq + l0 + tx] = tile[tx][ty+j];
}

// g_yt (B,H,L) -> g_v (B,L,H), v = gelu(y + D*h)
__global__ void transpose_bwd_kernel(const float* __restrict__ D){
  __shared__ float tile[32][33];
  int b  = blockIdx.z;
  int h0 = blockIdx.x*32;
  int l0 = blockIdx.y*32;
  int tx = threadIdx.x, ty = threadIdx.y;
  const float* in = g_yt + (size_t)b*Hdim*Lseq;
  float* out = g_v + (size_t)b*Lseq*Hdim;
  const float* hbuf = g_h + (size_t)b*Lseq*Hdim;
  #pragma unroll
  for (int j = 0; j < 32; j += 8)
    tile[ty+j][tx] = in[(size_t)(h0+ty+j)*Lseq + l0 + tx];
  __syncthreads();
  #pragma unroll
  for (int j = 0; j < 32; j += 8){
    size_t idx = (size_t)(l0+ty+j)*Hdim + h0 + tx;
    float y = tile[tx][ty+j] + D[h0+tx]*hbuf[idx];
    out[idx] = gelu_f(y);
  }
}

// ----------------- SSM param prep (per layer) -------------------------------
__global__ void prep_kernel(const float* __restrict__ Lre, const float* __restrict__ Lim,
                            const float* __restrict__ Pre, const float* __restrict__ Pim,
                            const float* __restrict__ Bre, const float* __restrict__ Bim,
                            const float* __restrict__ Cre, const float* __restrict__ Cim,
                            const float* __restrict__ logstep){
  int i = blockIdx.x*256 + threadIdx.x;
  if (i < HN){
    float pr = Pre[i], pi = Pim[i];
    float br = Bre[i], bi = Bim[i];
    float cr = Cre[i], ci = Cim[i];
    float w00r = cr*br + ci*bi, w00i = cr*bi - ci*br;  // conj(C)*B
    float w01r = cr*pr + ci*pi, w01i = cr*pi - ci*pr;  // conj(C)*P
    float w10r = pr*br + pi*bi, w10i = pr*bi - pi*br;  // conj(P)*B
    float w11r = pr*pr + pi*pi, w11i = 0.f;            // |P|^2
    g_pk01[i] = make_float4(w00r, w00i, w01r, w01i);
    g_pk23[i] = make_float4(w10r, w10i, w11r, w11i);
    g_plam[i] = make_float2(fminf(Lre[i], -1e-4f), Lim[i]);
    if (i < Hdim) g_2step[i] = 2.f*expf(-logstep[i]);
  }
}

// ----------------- Cauchy kernel: at_roots (H,2048) -------------------------
__global__ __launch_bounds__(256) void cauchy_kernel(){
  __shared__ float4 spk01[Nst];
  __shared__ float4 spk23[Nst];
  __shared__ float2 slam [Nst];
  int tid = threadIdx.x;
  int h = blockIdx.y;
  int l = blockIdx.x*256 + tid;
  if (tid < Nst){
    spk01[tid] = g_pk01[h*Nst + tid];
    spk23[tid] = g_pk23[h*Nst + tid];
    slam [tid] = g_plam[h*Nst + tid];
  }
  __syncthreads();
  float t   = tanf((float)(3.141592653589793/2048.0)*(float)l);
  float gim = g_2step[h]*t;
  float k00r=0.f,k00i=0.f,k01r=0.f,k01i=0.f,k10r=0.f,k10i=0.f,k11r=0.f,k11i=0.f;
  #pragma unroll 8
  for (int n = 0; n < Nst; n++){
    float2 lam = slam[n];
    float dre = -lam.x;
    float dim = gim - lam.y;
    float inv = frcp_fast(dre*dre + dim*dim);
    float ir  =  dre*inv;
    float ii  = -dim*inv;
    float4 w01 = spk01[n];
    float4 w23 = spk23[n];
    k00r += w01.x*ir - w01.y*ii;  k00i += w01.x*ii + w01.y*ir;
    k01r += w01.z*ir - w01.w*ii;  k01i += w01.z*ii + w01.w*ir;
    k10r += w23.x*ir - w23.y*ii;  k10i += w23.x*ii + w23.y*ir;
    k11r += w23.z*ir - w23.w*ii;  k11i += w23.z*ii + w23.w*ir;
  }
  float denr = 1.f + k11r, deni = k11i;
  float dinv = frcp_fast(denr*denr + deni*deni);
  float qr = denr*dinv, qi = -deni*dinv;          // 1/(1+k11)
  float mr = k01r*k10r - k01i*k10i;
  float mi = k01r*k10i + k01i*k10r;               // k01*k10
  float cr = mr*qr - mi*qi, ci2 = mr*qi + mi*qr;  // k01*k10/(1+k11)
  float ar = k00r - cr, ai = k00i - ci2;
  // c = 1 + i*t  ->  at = (ar - t*ai) + i(ai + t*ar)
  g_ar[(size_t)h*Lseq + l] = make_float2(ar - t*ai, ai + t*ar);
}

// ----------------- shared-mem Stockham FFT(2048) -----------------------------
// INV=false: e^{-i}, INV=true: e^{+i} (unnormalized). Returns buffer with result.
template<bool INV>
__device__ __forceinline__ float2* fft2048_sm(float2* buf0, float2* buf1,
                                              const float2* stw, int tid){
  float2* src = buf0; float2* dst = buf1;
  #pragma unroll
  for (int st = 0; st < 11; st++){
    int s = 1 << st;
    __syncthreads();
    #pragma unroll
    for (int i = 0; i < 4; i++){
      int idx = tid + 256*i;          // 0..1023
      int sp  = idx & ~(s-1);         // p*s (also twiddle index)
      float2 a = src[idx];
      float2 b = src[idx + 1024];
      float2 w = stw[sp];
      if (INV) w.y = -w.y;
      float2 d = csub(a, b);
      int j0 = idx + sp;
      dst[j0]     = cadd(a, b);
      dst[j0 + s] = cmul(d, w);
    }
    float2* tp = src; src = dst; dst = tp;
  }
  __syncthreads();
  return src;
}

// ----------------- Kd kernel: at_roots -> K -> rfft4096(K) -------------------
__global__ __launch_bounds__(256) void kd_kernel(){
  __shared__ float2 sA[2048];
  __shared__ float2 sB[2048];
  __shared__ float2 stw[1024];
  int tid = threadIdx.x;
  int h = blockIdx.x;
  for (int i = tid; i < 1024; i += 256) stw[i] = g_twA[i];
  const float2* ar = g_ar + (size_t)h*Lseq;
  #pragma unroll
  for (int i = 0; i < 8; i++){ int k = tid + 256*i; sA[k] = ar[k]; }
  // K = Re(ifft2048(at_roots))  (scale 1/2048 applied at pack)
  float2* K = fft2048_sm<true>(sA, sB, stw, tid);
  float2* Ob = (K == sA) ? sB : sA;
  const float sc = 1.f/2048.f;
  #pragma unroll
  for (int i = 0; i < 8; i++){
    int n = tid + 256*i;
    float2 v = make_float2(0.f, 0.f);
    if (n < 1024) v = make_float2(K[2*n].x*sc, K[2*n+1].x*sc);
    Ob[n] = v;
  }
  // forward FFT of packed K
  float2* Zp = fft2048_sm<false>(Ob, K, stw, tid);
  float2* outKd = g_Kd + (size_t)h*2049;
  #pragma unroll
  for (int i = 0; i < 8; i++){
    int k  = tid + 256*i;
    int kc = (2048 - k) & 2047;
    float2 zk = Zp[k], zc = Zp[kc];
    float2 E  = make_float2(0.5f*(zk.x+zc.x),  0.5f*(zk.y-zc.y));
    float2 Od = make_float2(0.5f*(zk.y+zc.y), -0.5f*(zk.x-zc.x));
    outKd[k] = cadd(E, cmul(g_twB[k], Od));
  }
  if (tid == 0){
    float2 z0 = Zp[0];
    outKd[2048] = make_float2(z0.x - z0.y, 0.f);
  }
}

// ----------------- conv kernel: one (b,h) causal FFT conv --------------------
__global__ __launch_bounds__(256) void conv_kernel(){
  __shared__ float2 sA[2048];
  __shared__ float2 sB[2048];
  __shared__ float2 stw[1024];
  __shared__ float2 sY2048;
  int tid = threadIdx.x;
  int h = blockIdx.x;
  int b = blockIdx.y;
  const float* u = g_ht + ((size_t)b*Hdim + h)*Lseq;
  for (int i = tid; i < 1024; i += 256) stw[i] = g_twA[i];
  #pragma unroll
  for (int i = 0; i < 4; i++){
    int n = tid + 256*i;                    // 0..1023
    sA[n]        = make_float2(u[2*n], u[2*n+1]);
    sA[n + 1024] = make_float2(0.f, 0.f);
  }
  float2* Z = fft2048_sm<false>(sA, sB, stw, tid);
  float2* O = (Z == sA) ? sB : sA;
  const float2* kd = g_Kd + (size_t)h*2049;
  // untangle -> spectrum U, multiply by Kd -> Y
  #pragma unroll
  for (int i = 0; i < 8; i++){
    int k  = tid + 256*i;
    int kc = (2048 - k) & 2047;
    float2 zk = Z[k], zc = Z[kc];
    float2 E  = make_float2(0.5f*(zk.x+zc.x),  0.5f*(zk.y-zc.y));
    float2 Od = make_float2(0.5f*(zk.y+zc.y), -0.5f*(zk.x-zc.x));
    float2 U  = cadd(E, cmul(g_twB[k], Od));
    O[k] = cmul(U, kd[k]);
  }
  if (tid == 0){
    float2 z0 = Z[0];
    float U2048 = z0.x - z0.y;
    float2 kv = kd[2048];
    sY2048 = make_float2(U2048*kv.x, U2048*kv.y);
  }
  __syncthreads();
  // retangle Y -> W packed spectrum
  #pragma unroll
  for (int i = 0; i < 8; i++){
    int k = tid + 256*i;
    float2 Yk = O[k];
    float2 Yc = (k == 0) ? sY2048 : O[2048 - k];
    float2 Ey = make_float2(0.5f*(Yk.x+Yc.x), 0.5f*(Yk.y-Yc.y));
    float2 Dm = make_float2(0.5f*(Yk.x-Yc.x), 0.5f*(Yk.y+Yc.y));
    float2 tb = g_twB[k];
    float2 Oy = cmul(Dm, make_float2(tb.x, -tb.y));   // * conj(t_k)
    Z[k] = make_float2(Ey.x - Oy.y, Ey.y + Oy.x);     // Ey + i*Oy
  }
  float2* w = fft2048_sm<true>(Z, O, stw, tid);
  float* out = g_yt + ((size_t)b*Hdim + h)*Lseq;
  const float sc = 1.f/2048.f;
  #pragma unroll
  for (int i = 0; i < 4; i++){
    int n = tid + 256*i;     // first 2048 time samples only
    float2 v = w[n];
    out[2*n]   = v.x*sc;
    out[2*n+1] = v.y*sc;
  }
}

// ----------------- SGEMM 128x128x8, 256 threads, 8x8 micro ------------------
// mode 0: C = acc+bias      mode 1: C = gelu(acc+bias)
// mode 2: C += aux*sigmoid(acc+bias)      mode 3: C += acc+bias
__global__ __launch_bounds__(256) void sgemm_kernel(const float* __restrict__ A,
                                                    const float* __restrict__ Bw,
                                                    const float* __restrict__ bias,
                                                    const float* __restrict__ aux,
                                                    float* __restrict__ C, int mode){
  __shared__ float As[8][128];
  __shared__ float Bs[8][128];
  int tid = threadIdx.x;
  int bm = blockIdx.y*128;
  int bn = blockIdx.x*128;
  int arow  = tid >> 1;
  int acol4 = (tid & 1)*4;
  int brow  = tid >> 5;
  int bcol4 = (tid & 31)*4;
  const float* Aptr = A  + (size_t)(bm + arow)*Hdim + acol4;
  const float* Bptr = Bw + (size_t)brow*Hdim + bn + bcol4;
  int ty = tid >> 4, tx = tid & 15;
  int ro = ty*8, co = tx*8;
  float acc[8][8];
  #pragma unroll
  for (int i = 0; i < 8; i++)
    #pragma unroll
    for (int j = 0; j < 8; j++) acc[i][j] = 0.f;

  for (int k0 = 0; k0 < Hdim; k0 += 8){
    float4 av = *(const float4*)(Aptr + k0);
    float4 bv = *(const float4*)(Bptr + (size_t)k0*Hdim);
    __syncthreads();
    As[acol4+0][arow] = av.x;
    As[acol4+1][arow] = av.y;
    As[acol4+2][arow] = av.z;
    As[acol4+3][arow] = av.w;
    *(float4*)(&Bs[brow][bcol4]) = bv;
    __syncthreads();
    #pragma unroll
    for (int kk = 0; kk < 8; kk++){
      float a[8], bb[8];
      *(float4*)(a)    = *(const float4*)(&As[kk][ro]);
      *(float4*)(a+4)  = *(const float4*)(&As[kk][ro+4]);
      *(float4*)(bb)   = *(const float4*)(&Bs[kk][co]);
      *(float4*)(bb+4) = *(const float4*)(&Bs[kk][co+4]);
      #pragma unroll
      for (int ii = 0; ii < 8; ii++)
        #pragma unroll
        for (int jj = 0; jj < 8; jj++)
          acc[ii][jj] += a[ii]*bb[jj];
    }
  }
  // epilogue
  #pragma unroll
  for (int ii = 0; ii < 8; ii++){
    size_t gr = (size_t)(bm + ro + ii);
    float* crow = C + gr*Hdim;
    const float* xrow = aux + gr*Hdim;
    #pragma unroll
    for (int j4 = 0; j4 < 8; j4 += 4){
      int gc = bn + co + j4;
      float4 bv = *(const float4*)(bias + gc);
      float v0 = acc[ii][j4+0] + bv.x;
      float v1 = acc[ii][j4+1] + bv.y;
      float v2 = acc[ii][j4+2] + bv.z;
      float v3 = acc[ii][j4+3] + bv.w;
      float4 o;
      if (mode == 0){
        o = make_float4(v0, v1, v2, v3);
      } else if (mode == 1){
        o = make_float4(gelu_f(v0), gelu_f(v1), gelu_f(v2), gelu_f(v3));
      } else if (mode == 2){
        float4 cv = *(const float4*)(crow + gc);
        float4 avx = *(const float4*)(xrow + gc);
        o.x = cv.x + avx.x*sigm_f(v0);
        o.y = cv.y + avx.y*sigm_f(v1);
        o.z = cv.z + avx.z*sigm_f(v2);
        o.w = cv.w + avx.w*sigm_f(v3);
      } else {
        float4 cv = *(const float4*)(crow + gc);
        o = make_float4(cv.x + v0, cv.y + v1, cv.z + v2, cv.w + v3);
      }
      *(float4*)(crow + gc) = o;
    }
  }
}

// ----------------- host driver ----------------------------------------------
extern "C" void kernel_launch(void* const* d_in, const int* in_sizes, int n_in,
                              void* d_out, int out_size){
  (void)in_sizes; (void)n_in; (void)out_size;
  const float* x     = (const float*)d_in[0];
  const float* sLre  = (const float*)d_in[1];
  const float* sLim  = (const float*)d_in[2];
  const float* sPre  = (const float*)d_in[3];
  const float* sPim  = (const float*)d_in[4];
  const float* sBre  = (const float*)d_in[5];
  const float* sBim  = (const float*)d_in[6];
  const float* sCre  = (const float*)d_in[7];
  const float* sCim  = (const float*)d_in[8];
  const float* sD    = (const float*)d_in[9];
  const float* sLog  = (const float*)d_in[10];
  const float* sb_ls = (const float*)d_in[11];
  const float* sb_lb = (const float*)d_in[12];
  const float* sb_W1 = (const float*)d_in[13];
  const float* sb_b1 = (const float*)d_in[14];
  const float* sb_W2 = (const float*)d_in[15];
  const float* sb_b2 = (const float*)d_in[16];
  const float* bk_ls = (const float*)d_in[17];
  const float* bk_lb = (const float*)d_in[18];
  const float* bk_W1 = (const float*)d_in[19];
  const float* bk_b1 = (const float*)d_in[20];
  const float* bk_W2 = (const float*)d_in[21];
  const float* bk_b2 = (const float*)d_in[22];

  float *p_x, *p_h, *p_v, *p_z1;
  cudaGetSymbolAddress((void**)&p_x,  g_x);
  cudaGetSymbolAddress((void**)&p_h,  g_h);
  cudaGetSymbolAddress((void**)&p_v,  g_v);
  cudaGetSymbolAddress((void**)&p_z1, g_z1);

  init_tw_kernel<<<8, 256>>>();
  cudaMemcpyAsync(p_x, x, (size_t)BLH*sizeof(float), cudaMemcpyDeviceToDevice);

  dim3 tblk(32, 8);
  dim3 tgrid(Hdim/32, Lseq/32, Bsz);
  dim3 ggrid(Hdim/128, NROW/128);

  for (int b = 0; b < 2; b++){
    for (int li = 0; li < 2; li++){
      int i = b*2 + li;
      ln_kernel<<<NROW/8, 256>>>(sb_ls + i*Hdim, sb_lb + i*Hdim);
      transpose_fwd_kernel<<<tgrid, tblk>>>();
      prep_kernel<<<(HN+255)/256, 256>>>(sLre + i*HN, sLim + i*HN, sPre + i*HN, sPim + i*HN,
                                         sBre + i*HN, sBim + i*HN, sCre + i*HN, sCim + i*HN,
                                         sLog + i*Hdim);
      cauchy_kernel<<<dim3(Lseq/256, Hdim), 256>>>();
      kd_kernel<<<Hdim, 256>>>();
      conv_kernel<<<dim3(Hdim, Bsz), 256>>>();
      transpose_bwd_kernel<<<tgrid, tblk>>>(sD + i*Hdim);
      sgemm_kernel<<<ggrid, 256>>>(p_v, sb_W1 + (size_t)i*HH, sb_b1 + i*Hdim, p_z1, p_z1, 0);
      sgemm_kernel<<<ggrid, 256>>>(p_v, sb_W2 + (size_t)i*HH, sb_b2 + i*Hdim, p_z1, p_x, 2);
    }
    ln_kernel<<<NROW/8, 256>>>(bk_ls + b*Hdim, bk_lb + b*Hdim);
    sgemm_kernel<<<ggrid, 256>>>(p_h,  bk_W1 + (size_t)b*HH, bk_b1 + b*Hdim, p_z1, p_z1, 1);
    sgemm_kernel<<<ggrid, 256>>>(p_z1, bk_W2 + (size_t)b*HH, bk_b2 + b*Hdim, p_z1, p_x, 3);
  }
  cudaMemcpyAsync(d_out, p_x, (size_t)BLH*sizeof(float), cudaMemcpyDeviceToDevice);
}

// round 4
// speedup vs baseline: 1.2986x; 1.2986x over previous
#include <cuda_runtime.h>
#include <cuda_bf16.h>
#include <cstdint>
#include <math.h>

#define Bsz   8
#define Lseq  2048
#define Hdim  512
#define Nst   64
#define NROW  (Bsz*Lseq)          // 16384
#define BLH   (Bsz*Lseq*Hdim)     // 8388608
#define HH    (Hdim*Hdim)
#define HN    (Hdim*Nst)

// ----------------- device scratch (no allocations allowed) ------------------
__device__ float  g_x [BLH];
__device__ float  g_h [BLH];
__device__ float  g_ht[BLH];
__device__ float  g_yt[BLH];
__device__ float  g_v [BLH];
__device__ float  g_z1[BLH];
__device__ float2 g_ar[Hdim*Lseq];        // at_roots (H, 2048)
__device__ float2 g_Kd[Hdim*2049];        // rfft4096(K) bins 0..2048
__device__ float4 g_pk01[HN];
__device__ float4 g_pk23[HN];
__device__ float2 g_plam[HN];
__device__ float  g_2step[Hdim];
__device__ float2 g_twA[1024];
__device__ float2 g_twB[2048];
// bf16 split operands for tensor-core GEMM
__device__ __nv_bfloat16 g_a0[BLH];
__device__ __nv_bfloat16 g_a1[BLH];
__device__ __nv_bfloat16 g_wt0[12*HH];    // transposed (n,k) hi
__device__ __nv_bfloat16 g_wt1[12*HH];    // transposed (n,k) lo

// ----------------- helpers --------------------------------------------------
__device__ __forceinline__ float2 cadd(float2 a, float2 b){ return make_float2(a.x+b.x, a.y+b.y); }
__device__ __forceinline__ float2 csub(float2 a, float2 b){ return make_float2(a.x-b.x, a.y-b.y); }
__device__ __forceinline__ float2 cmul(float2 a, float2 b){ return make_float2(a.x*b.x-a.y*b.y, a.x*b.y+a.y*b.x); }
__device__ __forceinline__ float frcp_fast(float x){ float y; asm("rcp.approx.f32 %0, %1;" : "=f"(y) : "f"(x)); return y; }
__device__ __forceinline__ float gelu_f(float x){
  float x3 = x*x*x;
  float t  = tanhf(0.7978845608028654f*(x + 0.044715f*x3));
  return 0.5f*x*(1.0f + t);
}
__device__ __forceinline__ float sigm_f(float x){ return 1.0f/(1.0f + __expf(-x)); }

__device__ __forceinline__ uint32_t smem_u32(const void* p){
  uint32_t a;
  asm("{ .reg .u64 t; cvta.to.shared.u64 t, %1; cvt.u32.u64 %0, t; }" : "=r"(a) : "l"(p));
  return a;
}
__device__ __forceinline__ void cp16(uint32_t saddr, const void* g){
  asm volatile("cp.async.ca.shared.global [%0], [%1], 16;" :: "r"(saddr), "l"(g));
}
#define CP_COMMIT() asm volatile("cp.async.commit_group;" ::: "memory")

__device__ __forceinline__ void ldsm4(uint32_t* r, uint32_t addr){
  asm volatile("ldmatrix.sync.aligned.m8n8.x4.shared.b16 {%0,%1,%2,%3}, [%4];"
    : "=r"(r[0]), "=r"(r[1]), "=r"(r[2]), "=r"(r[3]) : "r"(addr));
}
__device__ __forceinline__ void mma16816(float* c, const uint32_t* a, const uint32_t* b){
  asm volatile("mma.sync.aligned.m16n8k16.row.col.f32.bf16.bf16.f32 "
    "{%0,%1,%2,%3}, {%4,%5,%6,%7}, {%8,%9}, {%0,%1,%2,%3};"
    : "+f"(c[0]), "+f"(c[1]), "+f"(c[2]), "+f"(c[3])
    : "r"(a[0]), "r"(a[1]), "r"(a[2]), "r"(a[3]), "r"(b[0]), "r"(b[1]));
}

// ----------------- twiddle init ---------------------------------------------
__global__ void init_tw_kernel(){
  int i = blockIdx.x*256 + threadIdx.x;
  if (i < 1024){
    float a = (float)(6.283185307179586/2048.0) * (float)i;
    float s, c; sincosf(a, &s, &c);
    g_twA[i] = make_float2(c, -s);
  }
  if (i < 2048){
    float a = (float)(3.141592653589793/2048.0) * (float)i;
    float s, c; sincosf(a, &s, &c);
    g_twB[i] = make_float2(c, -s);
  }
}

// ----------------- layernorm: g_x -> g_h ------------------------------------
__global__ __launch_bounds__(256) void ln_kernel(const float* __restrict__ sc,
                                                 const float* __restrict__ bi){
  int warp = threadIdx.x >> 5, lane = threadIdx.x & 31;
  size_t row = (size_t)blockIdx.x*8 + warp;
  const float4* xr = (const float4*)(g_x + row*Hdim);
  float4 v[4];
  float s = 0.f, s2 = 0.f;
  #pragma unroll
  for (int i = 0; i < 4; i++){
    float4 t = xr[lane + 32*i];
    v[i] = t;
    s  += t.x + t.y + t.z + t.w;
    s2 += t.x*t.x + t.y*t.y + t.z*t.z + t.w*t.w;
  }
  #pragma unroll
  for (int o = 16; o; o >>= 1){
    s  += __shfl_xor_sync(0xffffffffu, s,  o);
    s2 += __shfl_xor_sync(0xffffffffu, s2, o);
  }
  float mean = s*(1.f/Hdim);
  float var  = s2*(1.f/Hdim) - mean*mean;
  float inv  = rsqrtf(var + 1e-6f);
  float4* orow = (float4*)(g_h + row*Hdim);
  const float4* s4 = (const float4*)sc;
  const float4* b4 = (const float4*)bi;
  #pragma unroll
  for (int i = 0; i < 4; i++){
    int ci = lane + 32*i;
    float4 sv = s4[ci], bv = b4[ci], t = v[i], o;
    o.x = (t.x-mean)*inv*sv.x + bv.x;
    o.y = (t.y-mean)*inv*sv.y + bv.y;
    o.z = (t.z-mean)*inv*sv.z + bv.z;
    o.w = (t.w-mean)*inv*sv.w + bv.w;
    orow[ci] = o;
  }
}

// ----------------- transposes -----------------------------------------------
__global__ void transpose_fwd_kernel(){
  __shared__ float tile[32][33];
  int b  = blockIdx.z;
  int h0 = blockIdx.x*32;
  int l0 = blockIdx.y*32;
  int tx = threadIdx.x, ty = threadIdx.y;
  const float* in = g_h + (size_t)b*Lseq*Hdim;
  float* out = g_ht + (size_t)b*Hdim*Lseq;
  #pragma unroll
  for (int j = 0; j < 32; j += 8)
    tile[ty+j][tx] = in[(size_t)(l0+ty+j)*Hdim + h0 + tx];
  __syncthreads();
  #pragma unroll
  for (int j = 0; j < 32; j += 8)
    out[(size_t)(h0+ty+j)*Lseq + l0 + tx] = tile[tx][ty+j];
}

// g_yt (B,H,L) -> g_v (B,L,H), v = gelu(y + D*h); also write bf16 split of v
__global__ void transpose_bwd_kernel(const float* __restrict__ D){
  __shared__ float tile[32][33];
  int b  = blockIdx.z;
  int h0 = blockIdx.x*32;
  int l0 = blockIdx.y*32;
  int tx = threadIdx.x, ty = threadIdx.y;
  const float* in = g_yt + (size_t)b*Hdim*Lseq;
  float* out = g_v + (size_t)b*Lseq*Hdim;
  const float* hbuf = g_h + (size_t)b*Lseq*Hdim;
  #pragma unroll
  for (int j = 0; j < 32; j += 8)
    tile[ty+j][tx] = in[(size_t)(h0+ty+j)*Lseq + l0 + tx];
  __syncthreads();
  size_t boff = (size_t)b*Lseq*Hdim;
  #pragma unroll
  for (int j = 0; j < 32; j += 8){
    size_t idx = (size_t)(l0+ty+j)*Hdim + h0 + tx;
    float y = tile[tx][ty+j] + D[h0+tx]*hbuf[idx];
    float g = gelu_f(y);
    out[idx] = g;
    __nv_bfloat16 hi = __float2bfloat16_rn(g);
    float r = g - __bfloat162float(hi);
    g_a0[boff + idx] = hi;
    g_a1[boff + idx] = __float2bfloat16_rn(r);
  }
}

// ----------------- split fp32 -> bf16 hi/lo ---------------------------------
__global__ __launch_bounds__(256) void split_kernel(const float* __restrict__ X){
  size_t i = ((size_t)blockIdx.x*256 + threadIdx.x)*4;
  float4 v = *(const float4*)(X + i);
  __nv_bfloat16 h0 = __float2bfloat16_rn(v.x);
  __nv_bfloat16 h1 = __float2bfloat16_rn(v.y);
  __nv_bfloat16 h2 = __float2bfloat16_rn(v.z);
  __nv_bfloat16 h3 = __float2bfloat16_rn(v.w);
  __nv_bfloat162 p0; p0.x = h0; p0.y = h1;
  __nv_bfloat162 p1; p1.x = h2; p1.y = h3;
  *(__nv_bfloat162*)(g_a0 + i)     = p0;
  *(__nv_bfloat162*)(g_a0 + i + 2) = p1;
  __nv_bfloat162 q0, q1;
  q0.x = __float2bfloat16_rn(v.x - __bfloat162float(h0));
  q0.y = __float2bfloat16_rn(v.y - __bfloat162float(h1));
  q1.x = __float2bfloat16_rn(v.z - __bfloat162float(h2));
  q1.y = __float2bfloat16_rn(v.w - __bfloat162float(h3));
  *(__nv_bfloat162*)(g_a1 + i)     = q0;
  *(__nv_bfloat162*)(g_a1 + i + 2) = q1;
}

// ----------------- weight transpose + split: W(k,n) -> Wt(n,k) hi/lo --------
__global__ void wprep_kernel(const float* __restrict__ W, int widx){
  __shared__ float tile[32][33];
  int n0 = blockIdx.x*32, k0 = blockIdx.y*32;
  int tx = threadIdx.x, ty = threadIdx.y;
  #pragma unroll
  for (int j = 0; j < 32; j += 8)
    tile[ty+j][tx] = W[(size_t)(k0+ty+j)*Hdim + n0 + tx];
  __syncthreads();
  size_t base = (size_t)widx*HH;
  #pragma unroll
  for (int j = 0; j < 32; j += 8){
    float a = tile[tx][ty+j];                       // W[k0+tx][n0+ty+j]
    size_t o = base + (size_t)(n0+ty+j)*Hdim + k0 + tx;
    __nv_bfloat16 hi = __float2bfloat16_rn(a);
    g_wt0[o] = hi;
    g_wt1[o] = __float2bfloat16_rn(a - __bfloat162float(hi));
  }
}

// ----------------- SSM param prep -------------------------------------------
__global__ void prep_kernel(const float* __restrict__ Lre, const float* __restrict__ Lim,
                            const float* __restrict__ Pre, const float* __restrict__ Pim,
                            const float* __restrict__ Bre, const float* __restrict__ Bim,
                            const float* __restrict__ Cre, const float* __restrict__ Cim,
                            const float* __restrict__ logstep){
  int i = blockIdx.x*256 + threadIdx.x;
  if (i < HN){
    float pr = Pre[i], pi = Pim[i];
    float br = Bre[i], bi = Bim[i];
    float cr = Cre[i], ci = Cim[i];
    float w00r = cr*br + ci*bi, w00i = cr*bi - ci*br;
    float w01r = cr*pr + ci*pi, w01i = cr*pi - ci*pr;
    float w10r = pr*br + pi*bi, w10i = pr*bi - pi*br;
    float w11r = pr*pr + pi*pi;
    g_pk01[i] = make_float4(w00r, w00i, w01r, w01i);
    g_pk23[i] = make_float4(w10r, w10i, w11r, 0.f);
    g_plam[i] = make_float2(fminf(Lre[i], -1e-4f), Lim[i]);
    if (i < Hdim) g_2step[i] = 2.f*expf(-logstep[i]);
  }
}

// ----------------- Cauchy kernel --------------------------------------------
__global__ __launch_bounds__(256) void cauchy_kernel(){
  __shared__ float4 spk01[Nst];
  __shared__ float4 spk23[Nst];
  __shared__ float2 slam [Nst];
  int tid = threadIdx.x;
  int h = blockIdx.y;
  int l = blockIdx.x*256 + tid;
  if (tid < Nst){
    spk01[tid] = g_pk01[h*Nst + tid];
    spk23[tid] = g_pk23[h*Nst + tid];
    slam [tid] = g_plam[h*Nst + tid];
  }
  __syncthreads();
  float t   = tanf((float)(3.141592653589793/2048.0)*(float)l);
  float gim = g_2step[h]*t;
  float k00r=0.f,k00i=0.f,k01r=0.f,k01i=0.f,k10r=0.f,k10i=0.f,k11r=0.f,k11i=0.f;
  #pragma unroll 8
  for (int n = 0; n < Nst; n++){
    float2 lam = slam[n];
    float dre = -lam.x;
    float dim = gim - lam.y;
    float inv = frcp_fast(dre*dre + dim*dim);
    float ir  =  dre*inv;
    float ii  = -dim*inv;
    float4 w01 = spk01[n];
    float4 w23 = spk23[n];
    k00r += w01.x*ir - w01.y*ii;  k00i += w01.x*ii + w01.y*ir;
    k01r += w01.z*ir - w01.w*ii;  k01i += w01.z*ii + w01.w*ir;
    k10r += w23.x*ir - w23.y*ii;  k10i += w23.x*ii + w23.y*ir;
    k11r += w23.z*ir;             k11i += w23.z*ii;
  }
  float denr = 1.f + k11r, deni = k11i;
  float dinv = frcp_fast(denr*denr + deni*deni);
  float qr = denr*dinv, qi = -deni*dinv;
  float mr = k01r*k10r - k01i*k10i;
  float mi = k01r*k10i + k01i*k10r;
  float cr = mr*qr - mi*qi, ci2 = mr*qi + mi*qr;
  float ar = k00r - cr, ai = k00i - ci2;
  g_ar[(size_t)h*Lseq + l] = make_float2(ar - t*ai, ai + t*ar);
}

// ----------------- shared-mem Stockham FFT(2048) -----------------------------
template<bool INV>
__device__ __forceinline__ float2* fft2048_sm(float2* buf0, float2* buf1,
                                              const float2* stw, int tid){
  float2* src = buf0; float2* dst = buf1;
  #pragma unroll
  for (int st = 0; st < 11; st++){
    int s = 1 << st;
    __syncthreads();
    #pragma unroll
    for (int i = 0; i < 4; i++){
      int idx = tid + 256*i;
      int sp  = idx & ~(s-1);
      float2 a = src[idx];
      float2 b = src[idx + 1024];
      float2 w = stw[sp];
      if (INV) w.y = -w.y;
      float2 d = csub(a, b);
      int j0 = idx + sp;
      dst[j0]     = cadd(a, b);
      dst[j0 + s] = cmul(d, w);
    }
    float2* tp = src; src = dst; dst = tp;
  }
  __syncthreads();
  return src;
}

// ----------------- Kd kernel ------------------------------------------------
__global__ __launch_bounds__(256) void kd_kernel(){
  __shared__ float2 sA[2048];
  __shared__ float2 sB[2048];
  __shared__ float2 stw[1024];
  int tid = threadIdx.x;
  int h = blockIdx.x;
  for (int i = tid; i < 1024; i += 256) stw[i] = g_twA[i];
  const float2* ar = g_ar + (size_t)h*Lseq;
  #pragma unroll
  for (int i = 0; i < 8; i++){ int k = tid + 256*i; sA[k] = ar[k]; }
  float2* K = fft2048_sm<true>(sA, sB, stw, tid);
  float2* Ob = (K == sA) ? sB : sA;
  const float sc = 1.f/2048.f;
  #pragma unroll
  for (int i = 0; i < 8; i++){
    int n = tid + 256*i;
    float2 v = make_float2(0.f, 0.f);
    if (n < 1024) v = make_float2(K[2*n].x*sc, K[2*n+1].x*sc);
    Ob[n] = v;
  }
  float2* Zp = fft2048_sm<false>(Ob, K, stw, tid);
  float2* outKd = g_Kd + (size_t)h*2049;
  #pragma unroll
  for (int i = 0; i < 8; i++){
    int k  = tid + 256*i;
    int kc = (2048 - k) & 2047;
    float2 zk = Zp[k], zc = Zp[kc];
    float2 E  = make_float2(0.5f*(zk.x+zc.x),  0.5f*(zk.y-zc.y));
    float2 Od = make_float2(0.5f*(zk.y+zc.y), -0.5f*(zk.x-zc.x));
    outKd[k] = cadd(E, cmul(g_twB[k], Od));
  }
  if (tid == 0){
    float2 z0 = Zp[0];
    outKd[2048] = make_float2(z0.x - z0.y, 0.f);
  }
}

// ----------------- conv kernel ----------------------------------------------
__global__ __launch_bounds__(256) void conv_kernel(){
  __shared__ float2 sA[2048];
  __shared__ float2 sB[2048];
  __shared__ float2 stw[1024];
  __shared__ float2 sY2048;
  int tid = threadIdx.x;
  int h = blockIdx.x;
  int b = blockIdx.y;
  const float* u = g_ht + ((size_t)b*Hdim + h)*Lseq;
  for (int i = tid; i < 1024; i += 256) stw[i] = g_twA[i];
  #pragma unroll
  for (int i = 0; i < 4; i++){
    int n = tid + 256*i;
    sA[n]        = make_float2(u[2*n], u[2*n+1]);
    sA[n + 1024] = make_float2(0.f, 0.f);
  }
  float2* Z = fft2048_sm<false>(sA, sB, stw, tid);
  float2* O = (Z == sA) ? sB : sA;
  const float2* kd = g_Kd + (size_t)h*2049;
  #pragma unroll
  for (int i = 0; i < 8; i++){
    int k  = tid + 256*i;
    int kc = (2048 - k) & 2047;
    float2 zk = Z[k], zc = Z[kc];
    float2 E  = make_float2(0.5f*(zk.x+zc.x),  0.5f*(zk.y-zc.y));
    float2 Od = make_float2(0.5f*(zk.y+zc.y), -0.5f*(zk.x-zc.x));
    float2 U  = cadd(E, cmul(g_twB[k], Od));
    O[k] = cmul(U, kd[k]);
  }
  if (tid == 0){
    float2 z0 = Z[0];
    float U2048 = z0.x - z0.y;
    float2 kv = kd[2048];
    sY2048 = make_float2(U2048*kv.x, U2048*kv.y);
  }
  __syncthreads();
  #pragma unroll
  for (int i = 0; i < 8; i++){
    int k = tid + 256*i;
    float2 Yk = O[k];
    float2 Yc = (k == 0) ? sY2048 : O[2048 - k];
    float2 Ey = make_float2(0.5f*(Yk.x+Yc.x), 0.5f*(Yk.y-Yc.y));
    float2 Dm = make_float2(0.5f*(Yk.x-Yc.x), 0.5f*(Yk.y+Yc.y));
    float2 tb = g_twB[k];
    float2 Oy = cmul(Dm, make_float2(tb.x, -tb.y));
    Z[k] = make_float2(Ey.x - Oy.y, Ey.y + Oy.x);
  }
  float2* w = fft2048_sm<true>(Z, O, stw, tid);
  float* out = g_yt + ((size_t)b*Hdim + h)*Lseq;
  const float sc = 1.f/2048.f;
  #pragma unroll
  for (int i = 0; i < 4; i++){
    int n = tid + 256*i;
    float2 v = w[n];
    out[2*n]   = v.x*sc;
    out[2*n+1] = v.y*sc;
  }
}

// ----------------- HMMA GEMM: 128x128 tile, bf16x3 compensation -------------
// C(16384x512) = A(16384x512) * Wt^T, Wt stored (n,k).
// mode 0: C = acc+bias   mode 1: C = gelu(acc+bias)
// mode 2: C += aux*sigmoid(acc+bias)   mode 3: C += acc+bias
#define TROW    80                      // padded bytes per 32-col bf16 row
#define TBYTES  (128*TROW)              // 10240 per tile
#define STAGEB  (4*TBYTES)              // A0,A1,B0,B1
#define SMEM_GEMM (2*STAGEB)            // 81920

__global__ __launch_bounds__(256) void hgemm_kernel(
    const __nv_bfloat16* __restrict__ A0g, const __nv_bfloat16* __restrict__ A1g,
    const __nv_bfloat16* __restrict__ B0g, const __nv_bfloat16* __restrict__ B1g,
    const float* __restrict__ bias, const float* __restrict__ aux,
    float* __restrict__ C, int mode)
{
  extern __shared__ char smem[];
  uint32_t sb = smem_u32(smem);
  int tid = threadIdx.x, wid = tid >> 5, lid = tid & 31;
  int bn = blockIdx.x*128, bm = blockIdx.y*128;
  int mw = wid & 3, nw = wid >> 2;

  // loader mapping: thread -> (row, 2 columns of 16B)
  int lrow = tid >> 1;
  int lc0  = tid & 1;            // c = lc0 + 2*j, j=0,1

  // ldmatrix lane mapping
  int arow = lid & 15;
  int aoff = (lid >> 4) * 16;
  int brow = ((lid >> 4) << 3) + (lid & 7);
  int boff = ((lid >> 3) & 1) * 16;

  float acc[2][8][4];
  #pragma unroll
  for (int i = 0; i < 2; i++)
    #pragma unroll
    for (int j = 0; j < 8; j++)
      #pragma unroll
      for (int q = 0; q < 4; q++) acc[i][j][q] = 0.f;

  // prologue: load chunk 0 into stage 0
  #pragma unroll
  for (int j = 0; j < 2; j++){
    int c = lc0 + 2*j;
    uint32_t so = (uint32_t)lrow*TROW + (uint32_t)c*16;
    size_t ga = (size_t)(bm + lrow)*Hdim + c*8;
    size_t gb = (size_t)(bn + lrow)*Hdim + c*8;
    cp16(sb + so,             A0g + ga);
    cp16(sb + TBYTES   + so,  A1g + ga);
    cp16(sb + 2*TBYTES + so,  B0g + gb);
    cp16(sb + 3*TBYTES + so,  B1g + gb);
  }
  CP_COMMIT();

  for (int ch = 0; ch < 16; ch++){
    int st = ch & 1;
    if (ch < 15){
      uint32_t sbase = sb + (st^1)*STAGEB;
      int k0 = (ch+1)*32;
      #pragma unroll
      for (int j = 0; j < 2; j++){
        int c = lc0 + 2*j;
        uint32_t so = (uint32_t)lrow*TROW + (uint32_t)c*16;
        size_t ga = (size_t)(bm + lrow)*Hdim + k0 + c*8;
        size_t gb = (size_t)(bn + lrow)*Hdim + k0 + c*8;
        cp16(sbase + so,             A0g + ga);
        cp16(sbase + TBYTES   + so,  A1g + ga);
        cp16(sbase + 2*TBYTES + so,  B0g + gb);
        cp16(sbase + 3*TBYTES + so,  B1g + gb);
      }
      CP_COMMIT();
      asm volatile("cp.async.wait_group 1;" ::: "memory");
    } else {
      asm volatile("cp.async.wait_group 0;" ::: "memory");
    }
    __syncthreads();

    uint32_t sA0 = sb + st*STAGEB;
    uint32_t sA1 = sA0 + TBYTES;
    uint32_t sB0 = sA0 + 2*TBYTES;
    uint32_t sB1 = sA0 + 3*TBYTES;
    #pragma unroll
    for (int ks = 0; ks < 2; ks++){
      int kb = ks*32;
      uint32_t a0f[2][4], a1f[2][4], b0f[4][4], b1f[4][4];
      #pragma unroll
      for (int mi = 0; mi < 2; mi++){
        uint32_t ro = (uint32_t)(mw*32 + mi*16 + arow)*TROW + kb + aoff;
        ldsm4(a0f[mi], sA0 + ro);
        ldsm4(a1f[mi], sA1 + ro);
      }
      #pragma unroll
      for (int nj = 0; nj < 4; nj++){
        uint32_t ro = (uint32_t)(nw*64 + nj*16 + brow)*TROW + kb + boff;
        ldsm4(b0f[nj], sB0 + ro);
        ldsm4(b1f[nj], sB1 + ro);
      }
      #pragma unroll
      for (int mi = 0; mi < 2; mi++){
        #pragma unroll
        for (int nt = 0; nt < 8; nt++){
          int nj = nt >> 1, sub = (nt & 1)*2;
          mma16816(acc[mi][nt], a0f[mi], &b0f[nj][sub]);
          mma16816(acc[mi][nt], a1f[mi], &b0f[nj][sub]);
          mma16816(acc[mi][nt], a0f[mi], &b1f[nj][sub]);
        }
      }
    }
    __syncthreads();
  }

  // epilogue
  int qr = lid >> 2, qc = (lid & 3)*2;
  #pragma unroll
  for (int mi = 0; mi < 2; mi++){
    #pragma unroll
    for (int hf = 0; hf < 2; hf++){
      int row = bm + mw*32 + mi*16 + hf*8 + qr;
      float* crow = C + (size_t)row*Hdim;
      const float* xrow = aux + (size_t)row*Hdim;
      #pragma unroll
      for (int nt = 0; nt < 8; nt++){
        int col = bn + nw*64 + nt*8 + qc;
        float2 bv = *(const float2*)(bias + col);
        float v0 = acc[mi][nt][hf*2+0] + bv.x;
        float v1 = acc[mi][nt][hf*2+1] + bv.y;
        float2 o;
        if (mode == 0){
          o = make_float2(v0, v1);
        } else if (mode == 1){
          o = make_float2(gelu_f(v0), gelu_f(v1));
        } else if (mode == 2){
          float2 cv = *(const float2*)(crow + col);
          float2 av = *(const float2*)(xrow + col);
          o.x = cv.x + av.x*sigm_f(v0);
          o.y = cv.y + av.y*sigm_f(v1);
        } else {
          float2 cv = *(const float2*)(crow + col);
          o = make_float2(cv.x + v0, cv.y + v1);
        }
        *(float2*)(crow + col) = o;
      }
    }
  }
}

// ----------------- host driver ----------------------------------------------
extern "C" void kernel_launch(void* const* d_in, const int* in_sizes, int n_in,
                              void* d_out, int out_size){
  (void)in_sizes; (void)n_in; (void)out_size;
  const float* x     = (const float*)d_in[0];
  const float* sLre  = (const float*)d_in[1];
  const float* sLim  = (const float*)d_in[2];
  const float* sPre  = (const float*)d_in[3];
  const float* sPim  = (const float*)d_in[4];
  const float* sBre  = (const float*)d_in[5];
  const float* sBim  = (const float*)d_in[6];
  const float* sCre  = (const float*)d_in[7];
  const float* sCim  = (const float*)d_in[8];
  const float* sD    = (const float*)d_in[9];
  const float* sLog  = (const float*)d_in[10];
  const float* sb_ls = (const float*)d_in[11];
  const float* sb_lb = (const float*)d_in[12];
  const float* sb_W1 = (const float*)d_in[13];
  const float* sb_b1 = (const float*)d_in[14];
  const float* sb_W2 = (const float*)d_in[15];
  const float* sb_b2 = (const float*)d_in[16];
  const float* bk_ls = (const float*)d_in[17];
  const float* bk_lb = (const float*)d_in[18];
  const float* bk_W1 = (const float*)d_in[19];
  const float* bk_b1 = (const float*)d_in[20];
  const float* bk_W2 = (const float*)d_in[21];
  const float* bk_b2 = (const float*)d_in[22];

  float *p_x, *p_h, *p_z1;
  __nv_bfloat16 *p_a0, *p_a1, *p_wt0, *p_wt1;
  cudaGetSymbolAddress((void**)&p_x,   g_x);
  cudaGetSymbolAddress((void**)&p_h,   g_h);
  cudaGetSymbolAddress((void**)&p_z1,  g_z1);
  cudaGetSymbolAddress((void**)&p_a0,  g_a0);
  cudaGetSymbolAddress((void**)&p_a1,  g_a1);
  cudaGetSymbolAddress((void**)&p_wt0, g_wt0);
  cudaGetSymbolAddress((void**)&p_wt1, g_wt1);

  cudaFuncSetAttribute(hgemm_kernel, cudaFuncAttributeMaxDynamicSharedMemorySize, SMEM_GEMM);

  init_tw_kernel<<<8, 256>>>();
  cudaMemcpyAsync(p_x, x, (size_t)BLH*sizeof(float), cudaMemcpyDeviceToDevice);

  dim3 wgrid(16, 16);
  dim3 tblk(32, 8);
  for (int i = 0; i < 4; i++){
    wprep_kernel<<<wgrid, tblk>>>(sb_W1 + (size_t)i*HH, i);
    wprep_kernel<<<wgrid, tblk>>>(sb_W2 + (size_t)i*HH, 4 + i);
  }
  for (int b = 0; b < 2; b++){
    wprep_kernel<<<wgrid, tblk>>>(bk_W1 + (size_t)b*HH, 8 + b);
    wprep_kernel<<<wgrid, tblk>>>(bk_W2 + (size_t)b*HH, 10 + b);
  }

  dim3 tgrid(Hdim/32, Lseq/32, Bsz);
  dim3 ggrid(Hdim/128, NROW/128);   // (4, 128)

  for (int b = 0; b < 2; b++){
    for (int li = 0; li < 2; li++){
      int i = b*2 + li;
      ln_kernel<<<NROW/8, 256>>>(sb_ls + i*Hdim, sb_lb + i*Hdim);
      transpose_fwd_kernel<<<tgrid, tblk>>>();
      prep_kernel<<<(HN+255)/256, 256>>>(sLre + i*HN, sLim + i*HN, sPre + i*HN, sPim + i*HN,
                                         sBre + i*HN, sBim + i*HN, sCre + i*HN, sCim + i*HN,
                                         sLog + i*Hdim);
      cauchy_kernel<<<dim3(Lseq/256, Hdim), 256>>>();
      kd_kernel<<<Hdim, 256>>>();
      conv_kernel<<<dim3(Hdim, Bsz), 256>>>();
      transpose_bwd_kernel<<<tgrid, tblk>>>(sD + i*Hdim);   // writes g_v + bf16 split
      hgemm_kernel<<<ggrid, 256, SMEM_GEMM>>>(p_a0, p_a1,
          p_wt0 + (size_t)i*HH, p_wt1 + (size_t)i*HH,
          sb_b1 + i*Hdim, p_z1, p_z1, 0);
      hgemm_kernel<<<ggrid, 256, SMEM_GEMM>>>(p_a0, p_a1,
          p_wt0 + (size_t)(4+i)*HH, p_wt1 + (size_t)(4+i)*HH,
          sb_b2 + i*Hdim, p_z1, p_x, 2);
    }
    ln_kernel<<<NROW/8, 256>>>(bk_ls + b*Hdim, bk_lb + b*Hdim);
    split_kernel<<<BLH/1024, 256>>>(p_h);
    hgemm_kernel<<<ggrid, 256, SMEM_GEMM>>>(p_a0, p_a1,
        p_wt0 + (size_t)(8+b)*HH, p_wt1 + (size_t)(8+b)*HH,
        bk_b1 + b*Hdim, p_z1, p_z1, 1);
    split_kernel<<<BLH/1024, 256>>>(p_z1);
    hgemm_kernel<<<ggrid, 256, SMEM_GEMM>>>(p_a0, p_a1,
        p_wt0 + (size_t)(10+b)*HH, p_wt1 + (size_t)(10+b)*HH,
        bk_b2 + b*Hdim, p_z1, p_x, 3);
  }
  cudaMemcpyAsync(d_out, p_x, (size_t)BLH*sizeof(float), cudaMemcpyDeviceToDevice);
}

// round 7
// speedup vs baseline: 1.6108x; 1.2404x over previous
#include <cuda_runtime.h>
#include <cuda_bf16.h>
#include <cstdint>
#include <math.h>

#define Bsz   8
#define Lseq  2048
#define Hdim  512
#define Nst   64
#define NROW  (Bsz*Lseq)          // 16384
#define BLH   (Bsz*Lseq*Hdim)     // 8388608
#define HH    (Hdim*Hdim)
#define HN    (Hdim*Nst)

// ----------------- device scratch (no allocations allowed) ------------------
__device__ float  g_x [BLH];
__device__ float  g_h [BLH];
__device__ float  g_ht[BLH];
__device__ float  g_yt[BLH];
__device__ float  g_v [BLH];
__device__ float  g_z1[BLH];
__device__ float2 g_ar[Hdim*Lseq];        // at_roots (H, 2048)
__device__ float2 g_Kd[Hdim*2049];        // rfft4096(K) bins 0..2048
__device__ float4 g_pk01[HN];
__device__ float4 g_pk23[HN];
__device__ float2 g_plam[HN];
__device__ float  g_2step[Hdim];
__device__ float2 g_twA[1024];
__device__ float2 g_twB[2048];
// bf16 split operands for tensor-core GEMM
__device__ __nv_bfloat16 g_a0[BLH];
__device__ __nv_bfloat16 g_a1[BLH];
__device__ __nv_bfloat16 g_b0[BLH];       // second split buffer (race-free fused split)
__device__ __nv_bfloat16 g_b1[BLH];
__device__ __nv_bfloat16 g_wt0[12*HH];    // transposed (n,k) hi
__device__ __nv_bfloat16 g_wt1[12*HH];    // transposed (n,k) lo

// ----------------- helpers --------------------------------------------------
__device__ __forceinline__ float2 cadd(float2 a, float2 b){ return make_float2(a.x+b.x, a.y+b.y); }
__device__ __forceinline__ float2 csub(float2 a, float2 b){ return make_float2(a.x-b.x, a.y-b.y); }
__device__ __forceinline__ float2 cmul(float2 a, float2 b){ return make_float2(a.x*b.x-a.y*b.y, a.x*b.y+a.y*b.x); }
__device__ __forceinline__ float frcp_fast(float x){ float y; asm("rcp.approx.f32 %0, %1;" : "=f"(y) : "f"(x)); return y; }
__device__ __forceinline__ float gelu_f(float x){
  float x3 = x*x*x;
  float t  = tanhf(0.7978845608028654f*(x + 0.044715f*x3));
  return 0.5f*x*(1.0f + t);
}
__device__ __forceinline__ float sigm_f(float x){ return 1.0f/(1.0f + __expf(-x)); }

__device__ __forceinline__ uint32_t smem_u32(const void* p){
  uint32_t a;
  asm("{ .reg .u64 t; cvta.to.shared.u64 t, %1; cvt.u32.u64 %0, t; }" : "=r"(a) : "l"(p));
  return a;
}
__device__ __forceinline__ void cp16(uint32_t saddr, const void* g){
  asm volatile("cp.async.ca.shared.global [%0], [%1], 16;" :: "r"(saddr), "l"(g));
}
#define CP_COMMIT() asm volatile("cp.async.commit_group;" ::: "memory")

__device__ __forceinline__ void ldsm4(uint32_t* r, uint32_t addr){
  asm volatile("ldmatrix.sync.aligned.m8n8.x4.shared.b16 {%0,%1,%2,%3}, [%4];"
    : "=r"(r[0]), "=r"(r[1]), "=r"(r[2]), "=r"(r[3]) : "r"(addr));
}
__device__ __forceinline__ void mma16816(float* c, const uint32_t* a, const uint32_t* b){
  asm volatile("mma.sync.aligned.m16n8k16.row.col.f32.bf16.bf16.f32 "
    "{%0,%1,%2,%3}, {%4,%5,%6,%7}, {%8,%9}, {%0,%1,%2,%3};"
    : "+f"(c[0]), "+f"(c[1]), "+f"(c[2]), "+f"(c[3])
    : "r"(a[0]), "r"(a[1]), "r"(a[2]), "r"(a[3]), "r"(b[0]), "r"(b[1]));
}

// ----------------- twiddle init ---------------------------------------------
__global__ void init_tw_kernel(){
  int i = blockIdx.x*256 + threadIdx.x;
  if (i < 1024){
    float a = (float)(6.283185307179586/2048.0) * (float)i;
    float s, c; sincosf(a, &s, &c);
    g_twA[i] = make_float2(c, -s);
  }
  if (i < 2048){
    float a = (float)(3.141592653589793/2048.0) * (float)i;
    float s, c; sincosf(a, &s, &c);
    g_twB[i] = make_float2(c, -s);
  }
}

// ----------------- layernorm: g_x -> g_h (+ optional bf16 split) ------------
__global__ __launch_bounds__(256) void ln_kernel(const float* __restrict__ sc,
                                                 const float* __restrict__ bi,
                                                 int wsplit){
  int warp = threadIdx.x >> 5, lane = threadIdx.x & 31;
  size_t row = (size_t)blockIdx.x*8 + warp;
  const float4* xr = (const float4*)(g_x + row*Hdim);
  float4 v[4];
  float s = 0.f, s2 = 0.f;
  #pragma unroll
  for (int i = 0; i < 4; i++){
    float4 t = xr[lane + 32*i];
    v[i] = t;
    s  += t.x + t.y + t.z + t.w;
    s2 += t.x*t.x + t.y*t.y + t.z*t.z + t.w*t.w;
  }
  #pragma unroll
  for (int o = 16; o; o >>= 1){
    s  += __shfl_xor_sync(0xffffffffu, s,  o);
    s2 += __shfl_xor_sync(0xffffffffu, s2, o);
  }
  float mean = s*(1.f/Hdim);
  float var  = s2*(1.f/Hdim) - mean*mean;
  float inv  = rsqrtf(var + 1e-6f);
  float4* orow = (float4*)(g_h + row*Hdim);
  const float4* s4 = (const float4*)sc;
  const float4* b4 = (const float4*)bi;
  #pragma unroll
  for (int i = 0; i < 4; i++){
    int ci = lane + 32*i;
    float4 sv = s4[ci], bv = b4[ci], t = v[i], o;
    o.x = (t.x-mean)*inv*sv.x + bv.x;
    o.y = (t.y-mean)*inv*sv.y + bv.y;
    o.z = (t.z-mean)*inv*sv.z + bv.z;
    o.w = (t.w-mean)*inv*sv.w + bv.w;
    orow[ci] = o;
    if (wsplit){
      size_t gi = row*Hdim + ci*4;
      __nv_bfloat16 h0 = __float2bfloat16_rn(o.x);
      __nv_bfloat16 h1 = __float2bfloat16_rn(o.y);
      __nv_bfloat16 h2 = __float2bfloat16_rn(o.z);
      __nv_bfloat16 h3 = __float2bfloat16_rn(o.w);
      __nv_bfloat162 p0; p0.x = h0; p0.y = h1;
      __nv_bfloat162 p1; p1.x = h2; p1.y = h3;
      *(__nv_bfloat162*)(g_a0 + gi)     = p0;
      *(__nv_bfloat162*)(g_a0 + gi + 2) = p1;
      __nv_bfloat162 q0, q1;
      q0.x = __float2bfloat16_rn(o.x - __bfloat162float(h0));
      q0.y = __float2bfloat16_rn(o.y - __bfloat162float(h1));
      q1.x = __float2bfloat16_rn(o.z - __bfloat162float(h2));
      q1.y = __float2bfloat16_rn(o.w - __bfloat162float(h3));
      *(__nv_bfloat162*)(g_a1 + gi)     = q0;
      *(__nv_bfloat162*)(g_a1 + gi + 2) = q1;
    }
  }
}

// ----------------- transposes -----------------------------------------------
__global__ void transpose_fwd_kernel(){
  __shared__ float tile[32][33];
  int b  = blockIdx.z;
  int h0 = blockIdx.x*32;
  int l0 = blockIdx.y*32;
  int tx = threadIdx.x, ty = threadIdx.y;
  const float* in = g_h + (size_t)b*Lseq*Hdim;
  float* out = g_ht + (size_t)b*Hdim*Lseq;
  #pragma unroll
  for (int j = 0; j < 32; j += 8)
    tile[ty+j][tx] = in[(size_t)(l0+ty+j)*Hdim + h0 + tx];
  __syncthreads();
  #pragma unroll
  for (int j = 0; j < 32; j += 8)
    out[(size_t)(h0+ty+j)*Lseq + l0 + tx] = tile[tx][ty+j];
}

// g_yt (B,H,L) -> g_v (B,L,H), v = gelu(y + D*h); also write bf16 split of v
__global__ void transpose_bwd_kernel(const float* __restrict__ D){
  __shared__ float tile[32][33];
  int b  = blockIdx.z;
  int h0 = blockIdx.x*32;
  int l0 = blockIdx.y*32;
  int tx = threadIdx.x, ty = threadIdx.y;
  const float* in = g_yt + (size_t)b*Hdim*Lseq;
  float* out = g_v + (size_t)b*Lseq*Hdim;
  const float* hbuf = g_h + (size_t)b*Lseq*Hdim;
  #pragma unroll
  for (int j = 0; j < 32; j += 8)
    tile[ty+j][tx] = in[(size_t)(h0+ty+j)*Lseq + l0 + tx];
  __syncthreads();
  size_t boff = (size_t)b*Lseq*Hdim;
  #pragma unroll
  for (int j = 0; j < 32; j += 8){
    size_t idx = (size_t)(l0+ty+j)*Hdim + h0 + tx;
    float y = tile[tx][ty+j] + D[h0+tx]*hbuf[idx];
    float g = gelu_f(y);
    out[idx] = g;
    __nv_bfloat16 hi = __float2bfloat16_rn(g);
    float r = g - __bfloat162float(hi);
    g_a0[boff + idx] = hi;
    g_a1[boff + idx] = __float2bfloat16_rn(r);
  }
}

// ----------------- weight transpose + split: W(k,n) -> Wt(n,k) hi/lo --------
__global__ void wprep_kernel(const float* __restrict__ W, int widx){
  __shared__ float tile[32][33];
  int n0 = blockIdx.x*32, k0 = blockIdx.y*32;
  int tx = threadIdx.x, ty = threadIdx.y;
  #pragma unroll
  for (int j = 0; j < 32; j += 8)
    tile[ty+j][tx] = W[(size_t)(k0+ty+j)*Hdim + n0 + tx];
  __syncthreads();
  size_t base = (size_t)widx*HH;
  #pragma unroll
  for (int j = 0; j < 32; j += 8){
    float a = tile[tx][ty+j];                       // W[k0+tx][n0+ty+j]
    size_t o = base + (size_t)(n0+ty+j)*Hdim + k0 + tx;
    __nv_bfloat16 hi = __float2bfloat16_rn(a);
    g_wt0[o] = hi;
    g_wt1[o] = __float2bfloat16_rn(a - __bfloat162float(hi));
  }
}

// ----------------- SSM param prep -------------------------------------------
__global__ void prep_kernel(const float* __restrict__ Lre, const float* __restrict__ Lim,
                            const float* __restrict__ Pre, const float* __restrict__ Pim,
                            const float* __restrict__ Bre, const float* __restrict__ Bim,
                            const float* __restrict__ Cre, const float* __restrict__ Cim,
                            const float* __restrict__ logstep){
  int i = blockIdx.x*256 + threadIdx.x;
  if (i < HN){
    float pr = Pre[i], pi = Pim[i];
    float br = Bre[i], bi = Bim[i];
    float cr = Cre[i], ci = Cim[i];
    float w00r = cr*br + ci*bi, w00i = cr*bi - ci*br;
    float w01r = cr*pr + ci*pi, w01i = cr*pi - ci*pr;
    float w10r = pr*br + pi*bi, w10i = pr*bi - pi*br;
    float w11r = pr*pr + pi*pi;
    g_pk01[i] = make_float4(w00r, w00i, w01r, w01i);
    g_pk23[i] = make_float4(w10r, w10i, w11r, 0.f);
    g_plam[i] = make_float2(fminf(Lre[i], -1e-4f), Lim[i]);
    if (i < Hdim) g_2step[i] = 2.f*expf(-logstep[i]);
  }
}

// ----------------- Cauchy kernel --------------------------------------------
__global__ __launch_bounds__(256) void cauchy_kernel(){
  __shared__ float4 spk01[Nst];
  __shared__ float4 spk23[Nst];
  __shared__ float2 slam [Nst];
  int tid = threadIdx.x;
  int h = blockIdx.y;
  int l = blockIdx.x*256 + tid;
  if (tid < Nst){
    spk01[tid] = g_pk01[h*Nst + tid];
    spk23[tid] = g_pk23[h*Nst + tid];
    slam [tid] = g_plam[h*Nst + tid];
  }
  __syncthreads();
  float t   = tanf((float)(3.141592653589793/2048.0)*(float)l);
  float gim = g_2step[h]*t;
  float k00r=0.f,k00i=0.f,k01r=0.f,k01i=0.f,k10r=0.f,k10i=0.f,k11r=0.f,k11i=0.f;
  #pragma unroll 8
  for (int n = 0; n < Nst; n++){
    float2 lam = slam[n];
    float dre = -lam.x;
    float dim = gim - lam.y;
    float inv = frcp_fast(dre*dre + dim*dim);
    float ir  =  dre*inv;
    float ii  = -dim*inv;
    float4 w01 = spk01[n];
    float4 w23 = spk23[n];
    k00r += w01.x*ir - w01.y*ii;  k00i += w01.x*ii + w01.y*ir;
    k01r += w01.z*ir - w01.w*ii;  k01i += w01.z*ii + w01.w*ir;
    k10r += w23.x*ir - w23.y*ii;  k10i += w23.x*ii + w23.y*ir;
    k11r += w23.z*ir;             k11i += w23.z*ii;
  }
  float denr = 1.f + k11r, deni = k11i;
  float dinv = frcp_fast(denr*denr + deni*deni);
  float qr = denr*dinv, qi = -deni*dinv;
  float mr = k01r*k10r - k01i*k10i;
  float mi = k01r*k10i + k01i*k10r;
  float cr = mr*qr - mi*qi, ci2 = mr*qi + mi*qr;
  float ar = k00r - cr, ai = k00i - ci2;
  g_ar[(size_t)h*Lseq + l] = make_float2(ar - t*ai, ai + t*ar);
}

// ----------------- shared-mem radix-4 Stockham FFT(2048) ---------------------
// 5 radix-4 stages (s=1,4,16,64,256) + final radix-2 (s=1024).
// Verified equal to the radix-2 chain on N=8 delta inputs (incl. +-i terms).
template<bool INV>
__device__ __forceinline__ float2* fft2048_r4(float2* buf0, float2* buf1,
                                              const float2* stw, int tid){
  float2* src = buf0; float2* dst = buf1;
  #pragma unroll
  for (int st = 0; st < 5; st++){
    int s = 1 << (2*st);
    __syncthreads();
    #pragma unroll
    for (int i = 0; i < 2; i++){
      int idx = tid + 256*i;            // 0..511
      int sp  = idx & ~(s-1);
      float2 a0 = src[idx];
      float2 a1 = src[idx + 512];
      float2 a2 = src[idx + 1024];
      float2 a3 = src[idx + 1536];
      float2 w1 = stw[sp];
      float2 w2 = stw[2*sp];
      if (INV){ w1.y = -w1.y; w2.y = -w2.y; }
      float2 w3 = cmul(w1, w2);
      float2 t0 = cadd(a0, a2), t1 = csub(a0, a2);
      float2 t2 = cadd(a1, a3), t3 = csub(a1, a3);
      float2 b0 = cadd(t0, t2);
      float2 b2 = csub(t0, t2);
      float2 b1, b3;
      if (!INV){
        b1 = make_float2(t1.x + t3.y, t1.y - t3.x);   // t1 - i t3
        b3 = make_float2(t1.x - t3.y, t1.y + t3.x);   // t1 + i t3
      } else {
        b1 = make_float2(t1.x - t3.y, t1.y + t3.x);
        b3 = make_float2(t1.x + t3.y, t1.y - t3.x);
      }
      int j = idx + 3*sp;
      dst[j]       = b0;
      dst[j + s]   = cmul(b1, w1);
      dst[j + 2*s] = cmul(b2, w2);
      dst[j + 3*s] = cmul(b3, w3);
    }
    float2* tp = src; src = dst; dst = tp;
  }
  // final radix-2, s = 1024 (twiddle = 1)
  __syncthreads();
  #pragma unroll
  for (int i = 0; i < 4; i++){
    int idx = tid + 256*i;              // 0..1023
    float2 a = src[idx];
    float2 b = src[idx + 1024];
    dst[idx]        = cadd(a, b);
    dst[idx + 1024] = csub(a, b);
  }
  float2* tp = src; src = dst; dst = tp;
  __syncthreads();
  return src;
}

// ----------------- Kd kernel ------------------------------------------------
__global__ __launch_bounds__(256) void kd_kernel(){
  __shared__ float2 sA[2048];
  __shared__ float2 sB[2048];
  __shared__ float2 stw[1024];
  int tid = threadIdx.x;
  int h = blockIdx.x;
  for (int i = tid; i < 1024; i += 256) stw[i] = g_twA[i];
  const float2* ar = g_ar + (size_t)h*Lseq;
  #pragma unroll
  for (int i = 0; i < 8; i++){ int k = tid + 256*i; sA[k] = ar[k]; }
  float2* K = fft2048_r4<true>(sA, sB, stw, tid);
  float2* Ob = (K == sA) ? sB : sA;
  const float sc = 1.f/2048.f;
  #pragma unroll
  for (int i = 0; i < 8; i++){
    int n = tid + 256*i;
    float2 v = make_float2(0.f, 0.f);
    if (n < 1024) v = make_float2(K[2*n].x*sc, K[2*n+1].x*sc);
    Ob[n] = v;
  }
  float2* Zp = fft2048_r4<false>(Ob, K, stw, tid);
  float2* outKd = g_Kd + (size_t)h*2049;
  #pragma unroll
  for (int i = 0; i < 8; i++){
    int k  = tid + 256*i;
    int kc = (2048 - k) & 2047;
    float2 zk = Zp[k], zc = Zp[kc];
    float2 E  = make_float2(0.5f*(zk.x+zc.x),  0.5f*(zk.y-zc.y));
    float2 Od = make_float2(0.5f*(zk.y+zc.y), -0.5f*(zk.x-zc.x));
    outKd[k] = cadd(E, cmul(g_twB[k], Od));
  }
  if (tid == 0){
    float2 z0 = Zp[0];
    outKd[2048] = make_float2(z0.x - z0.y, 0.f);
  }
}

// ----------------- conv kernel ----------------------------------------------
__global__ __launch_bounds__(256) void conv_kernel(){
  __shared__ float2 sA[2048];
  __shared__ float2 sB[2048];
  __shared__ float2 stw[1024];
  __shared__ float2 sY2048;
  int tid = threadIdx.x;
  int h = blockIdx.x;
  int b = blockIdx.y;
  const float* u = g_ht + ((size_t)b*Hdim + h)*Lseq;
  for (int i = tid; i < 1024; i += 256) stw[i] = g_twA[i];
  #pragma unroll
  for (int i = 0; i < 4; i++){
    int n = tid + 256*i;
    sA[n]        = make_float2(u[2*n], u[2*n+1]);
    sA[n + 1024] = make_float2(0.f, 0.f);
  }
  float2* Z = fft2048_r4<false>(sA, sB, stw, tid);
  float2* O = (Z == sA) ? sB : sA;
  const float2* kd = g_Kd + (size_t)h*2049;
  #pragma unroll
  for (int i = 0; i < 8; i++){
    int k  = tid + 256*i;
    int kc = (2048 - k) & 2047;
    float2 zk = Z[k], zc = Z[kc];
    float2 E  = make_float2(0.5f*(zk.x+zc.x),  0.5f*(zk.y-zc.y));
    float2 Od = make_float2(0.5f*(zk.y+zc.y), -0.5f*(zk.x-zc.x));
    float2 U  = cadd(E, cmul(g_twB[k], Od));
    O[k] = cmul(U, kd[k]);
  }
  if (tid == 0){
    float2 z0 = Z[0];
    float U2048 = z0.x - z0.y;
    float2 kv = kd[2048];
    sY2048 = make_float2(U2048*kv.x, U2048*kv.y);
  }
  __syncthreads();
  #pragma unroll
  for (int i = 0; i < 8; i++){
    int k = tid + 256*i;
    float2 Yk = O[k];
    float2 Yc = (k == 0) ? sY2048 : O[2048 - k];
    float2 Ey = make_float2(0.5f*(Yk.x+Yc.x), 0.5f*(Yk.y-Yc.y));
    float2 Dm = make_float2(0.5f*(Yk.x-Yc.x), 0.5f*(Yk.y+Yc.y));
    float2 tb = g_twB[k];
    float2 Oy = cmul(Dm, make_float2(tb.x, -tb.y));
    Z[k] = make_float2(Ey.x - Oy.y, Ey.y + Oy.x);
  }
  float2* w = fft2048_r4<true>(Z, O, stw, tid);
  float* out = g_yt + ((size_t)b*Hdim + h)*Lseq;
  const float sc = 1.f/2048.f;
  #pragma unroll
  for (int i = 0; i < 4; i++){
    int n = tid + 256*i;
    float2 v = w[n];
    out[2*n]   = v.x*sc;
    out[2*n+1] = v.y*sc;
  }
}

// ----------------- HMMA GEMM: 128x128 tile, bf16x3 compensation -------------
// mode 0: C = acc+bias   mode 1: C = gelu(acc+bias)
// mode 2: C += aux*sigmoid(acc+bias)   mode 3: C += acc+bias
// S0/S1 non-null: also write bf16 hi/lo split of output there (distinct from A!)
#define TROW    80                      // padded bytes per 32-col bf16 row
#define TBYTES  (128*TROW)              // 10240 per tile
#define STAGEB  (4*TBYTES)              // A0,A1,B0,B1
#define SMEM_GEMM (2*STAGEB)            // 81920

__global__ __launch_bounds__(256) void hgemm_kernel(
    const __nv_bfloat16* __restrict__ A0g, const __nv_bfloat16* __restrict__ A1g,
    const __nv_bfloat16* __restrict__ B0g, const __nv_bfloat16* __restrict__ B1g,
    const float* __restrict__ bias, const float* __restrict__ aux,
    float* __restrict__ C, int mode,
    __nv_bfloat16* __restrict__ S0, __nv_bfloat16* __restrict__ S1)
{
  extern __shared__ char smem[];
  uint32_t sb = smem_u32(smem);
  int tid = threadIdx.x, wid = tid >> 5, lid = tid & 31;
  int bn = blockIdx.x*128, bm = blockIdx.y*128;
  int mw = wid & 3, nw = wid >> 2;

  int lrow = tid >> 1;
  int lc0  = tid & 1;

  int arow = lid & 15;
  int aoff = (lid >> 4) * 16;
  int brow = ((lid >> 4) << 3) + (lid & 7);
  int boff = ((lid >> 3) & 1) * 16;

  float acc[2][8][4];
  #pragma unroll
  for (int i = 0; i < 2; i++)
    #pragma unroll
    for (int j = 0; j < 8; j++)
      #pragma unroll
      for (int q = 0; q < 4; q++) acc[i][j][q] = 0.f;

  #pragma unroll
  for (int j = 0; j < 2; j++){
    int c = lc0 + 2*j;
    uint32_t so = (uint32_t)lrow*TROW + (uint32_t)c*16;
    size_t ga = (size_t)(bm + lrow)*Hdim + c*8;
    size_t gb = (size_t)(bn + lrow)*Hdim + c*8;
    cp16(sb + so,             A0g + ga);
    cp16(sb + TBYTES   + so,  A1g + ga);
    cp16(sb + 2*TBYTES + so,  B0g + gb);
    cp16(sb + 3*TBYTES + so,  B1g + gb);
  }
  CP_COMMIT();

  for (int ch = 0; ch < 16; ch++){
    int st = ch & 1;
    if (ch < 15){
      uint32_t sbase = sb + (st^1)*STAGEB;
      int k0 = (ch+1)*32;
      #pragma unroll
      for (int j = 0; j < 2; j++){
        int c = lc0 + 2*j;
        uint32_t so = (uint32_t)lrow*TROW + (uint32_t)c*16;
        size_t ga = (size_t)(bm + lrow)*Hdim + k0 + c*8;
        size_t gb = (size_t)(bn + lrow)*Hdim + k0 + c*8;
        cp16(sbase + so,             A0g + ga);
        cp16(sbase + TBYTES   + so,  A1g + ga);
        cp16(sbase + 2*TBYTES + so,  B0g + gb);
        cp16(sbase + 3*TBYTES + so,  B1g + gb);
      }
      CP_COMMIT();
      asm volatile("cp.async.wait_group 1;" ::: "memory");
    } else {
      asm volatile("cp.async.wait_group 0;" ::: "memory");
    }
    __syncthreads();

    uint32_t sA0 = sb + st*STAGEB;
    uint32_t sA1 = sA0 + TBYTES;
    uint32_t sB0 = sA0 + 2*TBYTES;
    uint32_t sB1 = sA0 + 3*TBYTES;
    #pragma unroll
    for (int ks = 0; ks < 2; ks++){
      int kb = ks*32;
      uint32_t a0f[2][4], a1f[2][4], b0f[4][4], b1f[4][4];
      #pragma unroll
      for (int mi = 0; mi < 2; mi++){
        uint32_t ro = (uint32_t)(mw*32 + mi*16 + arow)*TROW + kb + aoff;
        ldsm4(a0f[mi], sA0 + ro);
        ldsm4(a1f[mi], sA1 + ro);
      }
      #pragma unroll
      for (int nj = 0; nj < 4; nj++){
        uint32_t ro = (uint32_t)(nw*64 + nj*16 + brow)*TROW + kb + boff;
        ldsm4(b0f[nj], sB0 + ro);
        ldsm4(b1f[nj], sB1 + ro);
      }
      #pragma unroll
      for (int mi = 0; mi < 2; mi++){
        #pragma unroll
        for (int nt = 0; nt < 8; nt++){
          int nj = nt >> 1, sub = (nt & 1)*2;
          mma16816(acc[mi][nt], a0f[mi], &b0f[nj][sub]);
          mma16816(acc[mi][nt], a1f[mi], &b0f[nj][sub]);
          mma16816(acc[mi][nt], a0f[mi], &b1f[nj][sub]);
        }
      }
    }
    __syncthreads();
  }

  // epilogue
  int qr = lid >> 2, qc = (lid & 3)*2;
  #pragma unroll
  for (int mi = 0; mi < 2; mi++){
    #pragma unroll
    for (int hf = 0; hf < 2; hf++){
      int row = bm + mw*32 + mi*16 + hf*8 + qr;
      float* crow = C + (size_t)row*Hdim;
      const float* xrow = aux + (size_t)row*Hdim;
      #pragma unroll
      for (int nt = 0; nt < 8; nt++){
        int col = bn + nw*64 + nt*8 + qc;
        float2 bv = *(const float2*)(bias + col);
        float v0 = acc[mi][nt][hf*2+0] + bv.x;
        float v1 = acc[mi][nt][hf*2+1] + bv.y;
        float2 o;
        if (mode == 0){
          o = make_float2(v0, v1);
        } else if (mode == 1){
          o = make_float2(gelu_f(v0), gelu_f(v1));
        } else if (mode == 2){
          float2 cv = *(const float2*)(crow + col);
          float2 av = *(const float2*)(xrow + col);
          o.x = cv.x + av.x*sigm_f(v0);
          o.y = cv.y + av.y*sigm_f(v1);
        } else {
          float2 cv = *(const float2*)(crow + col);
          o = make_float2(cv.x + v0, cv.y + v1);
        }
        *(float2*)(crow + col) = o;
        if (S0){
          size_t gi = (size_t)row*Hdim + col;
          __nv_bfloat16 h0 = __float2bfloat16_rn(o.x);
          __nv_bfloat16 h1 = __float2bfloat16_rn(o.y);
          __nv_bfloat162 p; p.x = h0; p.y = h1;
          *(__nv_bfloat162*)(S0 + gi) = p;
          __nv_bfloat162 q;
          q.x = __float2bfloat16_rn(o.x - __bfloat162float(h0));
          q.y = __float2bfloat16_rn(o.y - __bfloat162float(h1));
          *(__nv_bfloat162*)(S1 + gi) = q;
        }
      }
    }
  }
}

// ----------------- host driver ----------------------------------------------
extern "C" void kernel_launch(void* const* d_in, const int* in_sizes, int n_in,
                              void* d_out, int out_size){
  (void)in_sizes; (void)n_in; (void)out_size;
  const float* x     = (const float*)d_in[0];
  const float* sLre  = (const float*)d_in[1];
  const float* sLim  = (const float*)d_in[2];
  const float* sPre  = (const float*)d_in[3];
  const float* sPim  = (const float*)d_in[4];
  const float* sBre  = (const float*)d_in[5];
  const float* sBim  = (const float*)d_in[6];
  const float* sCre  = (const float*)d_in[7];
  const float* sCim  = (const float*)d_in[8];
  const float* sD    = (const float*)d_in[9];
  const float* sLog  = (const float*)d_in[10];
  const float* sb_ls = (const float*)d_in[11];
  const float* sb_lb = (const float*)d_in[12];
  const float* sb_W1 = (const float*)d_in[13];
  const float* sb_b1 = (const float*)d_in[14];
  const float* sb_W2 = (const float*)d_in[15];
  const float* sb_b2 = (const float*)d_in[16];
  const float* bk_ls = (const float*)d_in[17];
  const float* bk_lb = (const float*)d_in[18];
  const float* bk_W1 = (const float*)d_in[19];
  const float* bk_b1 = (const float*)d_in[20];
  const float* bk_W2 = (const float*)d_in[21];
  const float* bk_b2 = (const float*)d_in[22];

  float *p_x, *p_h, *p_z1;
  __nv_bfloat16 *p_a0, *p_a1, *p_b0, *p_b1, *p_wt0, *p_wt1;
  cudaGetSymbolAddress((void**)&p_x,   g_x);
  cudaGetSymbolAddress((void**)&p_h,   g_h);
  cudaGetSymbolAddress((void**)&p_z1,  g_z1);
  cudaGetSymbolAddress((void**)&p_a0,  g_a0);
  cudaGetSymbolAddress((void**)&p_a1,  g_a1);
  cudaGetSymbolAddress((void**)&p_b0,  g_b0);
  cudaGetSymbolAddress((void**)&p_b1,  g_b1);
  cudaGetSymbolAddress((void**)&p_wt0, g_wt0);
  cudaGetSymbolAddress((void**)&p_wt1, g_wt1);

  cudaFuncSetAttribute(hgemm_kernel, cudaFuncAttributeMaxDynamicSharedMemorySize, SMEM_GEMM);

  init_tw_kernel<<<8, 256>>>();                                   // launch 1
  cudaMemcpyAsync(p_x, x, (size_t)BLH*sizeof(float), cudaMemcpyDeviceToDevice);

  dim3 wgrid(16, 16);
  dim3 tblk(32, 8);
  dim3 tgrid(Hdim/32, Lseq/32, Bsz);
  dim3 ggrid(Hdim/128, NROW/128);   // (4, 128)

  for (int b = 0; b < 2; b++){
    for (int li = 0; li < 2; li++){
      int i = b*2 + li;
      ln_kernel<<<NROW/8, 256>>>(sb_ls + i*Hdim, sb_lb + i*Hdim, 0);   // launch 2
      transpose_fwd_kernel<<<tgrid, tblk>>>();                          // 3
      prep_kernel<<<(HN+255)/256, 256>>>(sLre + i*HN, sLim + i*HN, sPre + i*HN, sPim + i*HN,
                                         sBre + i*HN, sBim + i*HN, sCre + i*HN, sCim + i*HN,
                                         sLog + i*Hdim);                // 4
      cauchy_kernel<<<dim3(Lseq/256, Hdim), 256>>>();                   // 5 (profiled)
      kd_kernel<<<Hdim, 256>>>();
      conv_kernel<<<dim3(Hdim, Bsz), 256>>>();
      transpose_bwd_kernel<<<tgrid, tblk>>>(sD + i*Hdim);   // writes g_v + bf16 split
      wprep_kernel<<<wgrid, tblk>>>(sb_W1 + (size_t)i*HH, i);
      hgemm_kernel<<<ggrid, 256, SMEM_GEMM>>>(p_a0, p_a1,
          p_wt0 + (size_t)i*HH, p_wt1 + (size_t)i*HH,
          sb_b1 + i*Hdim, p_z1, p_z1, 0, nullptr, nullptr);
      wprep_kernel<<<wgrid, tblk>>>(sb_W2 + (size_t)i*HH, 4 + i);
      hgemm_kernel<<<ggrid, 256, SMEM_GEMM>>>(p_a0, p_a1,
          p_wt0 + (size_t)(4+i)*HH, p_wt1 + (size_t)(4+i)*HH,
          sb_b2 + i*Hdim, p_z1, p_x, 2, nullptr, nullptr);
    }
    ln_kernel<<<NROW/8, 256>>>(bk_ls + b*Hdim, bk_lb + b*Hdim, 1);  // h + split(h)->a0/a1
    wprep_kernel<<<wgrid, tblk>>>(bk_W1 + (size_t)b*HH, 8 + b);
    hgemm_kernel<<<ggrid, 256, SMEM_GEMM>>>(p_a0, p_a1,
        p_wt0 + (size_t)(8+b)*HH, p_wt1 + (size_t)(8+b)*HH,
        bk_b1 + b*Hdim, p_z1, p_z1, 1, p_b0, p_b1);   // split(z1)->b0/b1 (race-free)
    wprep_kernel<<<wgrid, tblk>>>(bk_W2 + (size_t)b*HH, 10 + b);
    hgemm_kernel<<<ggrid, 256, SMEM_GEMM>>>(p_b0, p_b1,
        p_wt0 + (size_t)(10+b)*HH, p_wt1 + (size_t)(10+b)*HH,
        bk_b2 + b*Hdim, p_z1, p_x, 3, nullptr, nullptr);
  }
  cudaMemcpyAsync(d_out, p_x, (size_t)BLH*sizeof(float), cudaMemcpyDeviceToDevice);
}

// round 8
// speedup vs baseline: 1.6617x; 1.0316x over previous
#include <cuda_runtime.h>
#include <cuda_bf16.h>
#include <cstdint>
#include <math.h>

#define Bsz   8
#define Lseq  2048
#define Hdim  512
#define Nst   64
#define NROW  (Bsz*Lseq)          // 16384
#define BLH   (Bsz*Lseq*Hdim)     // 8388608
#define HH    (Hdim*Hdim)
#define HN    (Hdim*Nst)
#define KDSZ  (Hdim*2049)

// ----------------- device scratch (no allocations allowed) ------------------
__device__ float  g_x [BLH];
__device__ float  g_h [BLH];
__device__ float  g_ht[BLH];
__device__ float  g_yt[BLH];
__device__ float  g_v [BLH];
__device__ float  g_z1[BLH];
__device__ float2 g_ar[Hdim*Lseq];        // at_roots (H, 2048) — serial reuse on s2
__device__ float2 g_KdL[4*KDSZ];          // per-layer rfft4096(K)
__device__ float2 g_twA[1024];
__device__ float2 g_twB[2048];
// bf16 split operands for tensor-core GEMM
__device__ __nv_bfloat16 g_a0[BLH];
__device__ __nv_bfloat16 g_a1[BLH];
__device__ __nv_bfloat16 g_b0[BLH];
__device__ __nv_bfloat16 g_b1[BLH];
__device__ __nv_bfloat16 g_wt0[12*HH];    // transposed (n,k) hi
__device__ __nv_bfloat16 g_wt1[12*HH];    // transposed (n,k) lo

// ----------------- helpers --------------------------------------------------
__device__ __forceinline__ float2 cadd(float2 a, float2 b){ return make_float2(a.x+b.x, a.y+b.y); }
__device__ __forceinline__ float2 csub(float2 a, float2 b){ return make_float2(a.x-b.x, a.y-b.y); }
__device__ __forceinline__ float2 cmul(float2 a, float2 b){ return make_float2(a.x*b.x-a.y*b.y, a.x*b.y+a.y*b.x); }
__device__ __forceinline__ float frcp_fast(float x){ float y; asm("rcp.approx.f32 %0, %1;" : "=f"(y) : "f"(x)); return y; }
__device__ __forceinline__ float gelu_f(float x){
  float x3 = x*x*x;
  float t  = tanhf(0.7978845608028654f*(x + 0.044715f*x3));
  return 0.5f*x*(1.0f + t);
}
__device__ __forceinline__ float sigm_f(float x){ return 1.0f/(1.0f + __expf(-x)); }

__device__ __forceinline__ uint32_t smem_u32(const void* p){
  uint32_t a;
  asm("{ .reg .u64 t; cvta.to.shared.u64 t, %1; cvt.u32.u64 %0, t; }" : "=r"(a) : "l"(p));
  return a;
}
__device__ __forceinline__ void cp16(uint32_t saddr, const void* g){
  asm volatile("cp.async.ca.shared.global [%0], [%1], 16;" :: "r"(saddr), "l"(g));
}
#define CP_COMMIT() asm volatile("cp.async.commit_group;" ::: "memory")

__device__ __forceinline__ void ldsm4(uint32_t* r, uint32_t addr){
  asm volatile("ldmatrix.sync.aligned.m8n8.x4.shared.b16 {%0,%1,%2,%3}, [%4];"
    : "=r"(r[0]), "=r"(r[1]), "=r"(r[2]), "=r"(r[3]) : "r"(addr));
}
__device__ __forceinline__ void mma16816(float* c, const uint32_t* a, const uint32_t* b){
  asm volatile("mma.sync.aligned.m16n8k16.row.col.f32.bf16.bf16.f32 "
    "{%0,%1,%2,%3}, {%4,%5,%6,%7}, {%8,%9}, {%0,%1,%2,%3};"
    : "+f"(c[0]), "+f"(c[1]), "+f"(c[2]), "+f"(c[3])
    : "r"(a[0]), "r"(a[1]), "r"(a[2]), "r"(a[3]), "r"(b[0]), "r"(b[1]));
}

// ----------------- twiddle init ---------------------------------------------
__global__ void init_tw_kernel(){
  int i = blockIdx.x*256 + threadIdx.x;
  if (i < 1024){
    float a = (float)(6.283185307179586/2048.0) * (float)i;
    float s, c; sincosf(a, &s, &c);
    g_twA[i] = make_float2(c, -s);
  }
  if (i < 2048){
    float a = (float)(3.141592653589793/2048.0) * (float)i;
    float s, c; sincosf(a, &s, &c);
    g_twB[i] = make_float2(c, -s);
  }
}

// ----------------- layernorm: g_x -> g_h (+ optional bf16 split) ------------
__global__ __launch_bounds__(256) void ln_kernel(const float* __restrict__ sc,
                                                 const float* __restrict__ bi,
                                                 int wsplit){
  int warp = threadIdx.x >> 5, lane = threadIdx.x & 31;
  size_t row = (size_t)blockIdx.x*8 + warp;
  const float4* xr = (const float4*)(g_x + row*Hdim);
  float4 v[4];
  float s = 0.f, s2 = 0.f;
  #pragma unroll
  for (int i = 0; i < 4; i++){
    float4 t = xr[lane + 32*i];
    v[i] = t;
    s  += t.x + t.y + t.z + t.w;
    s2 += t.x*t.x + t.y*t.y + t.z*t.z + t.w*t.w;
  }
  #pragma unroll
  for (int o = 16; o; o >>= 1){
    s  += __shfl_xor_sync(0xffffffffu, s,  o);
    s2 += __shfl_xor_sync(0xffffffffu, s2, o);
  }
  float mean = s*(1.f/Hdim);
  float var  = s2*(1.f/Hdim) - mean*mean;
  float inv  = rsqrtf(var + 1e-6f);
  float4* orow = (float4*)(g_h + row*Hdim);
  const float4* s4 = (const float4*)sc;
  const float4* b4 = (const float4*)bi;
  #pragma unroll
  for (int i = 0; i < 4; i++){
    int ci = lane + 32*i;
    float4 sv = s4[ci], bv = b4[ci], t = v[i], o;
    o.x = (t.x-mean)*inv*sv.x + bv.x;
    o.y = (t.y-mean)*inv*sv.y + bv.y;
    o.z = (t.z-mean)*inv*sv.z + bv.z;
    o.w = (t.w-mean)*inv*sv.w + bv.w;
    orow[ci] = o;
    if (wsplit){
      size_t gi = row*Hdim + ci*4;
      __nv_bfloat16 h0 = __float2bfloat16_rn(o.x);
      __nv_bfloat16 h1 = __float2bfloat16_rn(o.y);
      __nv_bfloat16 h2 = __float2bfloat16_rn(o.z);
      __nv_bfloat16 h3 = __float2bfloat16_rn(o.w);
      __nv_bfloat162 p0; p0.x = h0; p0.y = h1;
      __nv_bfloat162 p1; p1.x = h2; p1.y = h3;
      *(__nv_bfloat162*)(g_a0 + gi)     = p0;
      *(__nv_bfloat162*)(g_a0 + gi + 2) = p1;
      __nv_bfloat162 q0, q1;
      q0.x = __float2bfloat16_rn(o.x - __bfloat162float(h0));
      q0.y = __float2bfloat16_rn(o.y - __bfloat162float(h1));
      q1.x = __float2bfloat16_rn(o.z - __bfloat162float(h2));
      q1.y = __float2bfloat16_rn(o.w - __bfloat162float(h3));
      *(__nv_bfloat162*)(g_a1 + gi)     = q0;
      *(__nv_bfloat162*)(g_a1 + gi + 2) = q1;
    }
  }
}

// ----------------- transposes -----------------------------------------------
__global__ void transpose_fwd_kernel(){
  __shared__ float tile[32][33];
  int b  = blockIdx.z;
  int h0 = blockIdx.x*32;
  int l0 = blockIdx.y*32;
  int tx = threadIdx.x, ty = threadIdx.y;
  const float* in = g_h + (size_t)b*Lseq*Hdim;
  float* out = g_ht + (size_t)b*Hdim*Lseq;
  #pragma unroll
  for (int j = 0; j < 32; j += 8)
    tile[ty+j][tx] = in[(size_t)(l0+ty+j)*Hdim + h0 + tx];
  __syncthreads();
  #pragma unroll
  for (int j = 0; j < 32; j += 8)
    out[(size_t)(h0+ty+j)*Lseq + l0 + tx] = tile[tx][ty+j];
}

// g_yt (B,H,L) -> g_v (B,L,H), v = gelu(y + D*h); also write bf16 split of v
__global__ void transpose_bwd_kernel(const float* __restrict__ D){
  __shared__ float tile[32][33];
  int b  = blockIdx.z;
  int h0 = blockIdx.x*32;
  int l0 = blockIdx.y*32;
  int tx = threadIdx.x, ty = threadIdx.y;
  const float* in = g_yt + (size_t)b*Hdim*Lseq;
  float* out = g_v + (size_t)b*Lseq*Hdim;
  const float* hbuf = g_h + (size_t)b*Lseq*Hdim;
  #pragma unroll
  for (int j = 0; j < 32; j += 8)
    tile[ty+j][tx] = in[(size_t)(h0+ty+j)*Lseq + l0 + tx];
  __syncthreads();
  size_t boff = (size_t)b*Lseq*Hdim;
  #pragma unroll
  for (int j = 0; j < 32; j += 8){
    size_t idx = (size_t)(l0+ty+j)*Hdim + h0 + tx;
    float y = tile[tx][ty+j] + D[h0+tx]*hbuf[idx];
    float g = gelu_f(y);
    out[idx] = g;
    __nv_bfloat16 hi = __float2bfloat16_rn(g);
    float r = g - __bfloat162float(hi);
    g_a0[boff + idx] = hi;
    g_a1[boff + idx] = __float2bfloat16_rn(r);
  }
}

// ----------------- weight transpose + split: W(k,n) -> Wt(n,k) hi/lo --------
__global__ void wprep_kernel(const float* __restrict__ W, int widx){
  __shared__ float tile[32][33];
  int n0 = blockIdx.x*32, k0 = blockIdx.y*32;
  int tx = threadIdx.x, ty = threadIdx.y;
  #pragma unroll
  for (int j = 0; j < 32; j += 8)
    tile[ty+j][tx] = W[(size_t)(k0+ty+j)*Hdim + n0 + tx];
  __syncthreads();
  size_t base = (size_t)widx*HH;
  #pragma unroll
  for (int j = 0; j < 32; j += 8){
    float a = tile[tx][ty+j];                       // W[k0+tx][n0+ty+j]
    size_t o = base + (size_t)(n0+ty+j)*Hdim + k0 + tx;
    __nv_bfloat16 hi = __float2bfloat16_rn(a);
    g_wt0[o] = hi;
    g_wt1[o] = __float2bfloat16_rn(a - __bfloat162float(hi));
  }
}

// ----------------- Cauchy kernel (prep fused in) -----------------------------
__global__ __launch_bounds__(256) void cauchy_kernel(
    const float* __restrict__ Lre, const float* __restrict__ Lim,
    const float* __restrict__ Pre, const float* __restrict__ Pim,
    const float* __restrict__ Bre, const float* __restrict__ Bim,
    const float* __restrict__ Cre, const float* __restrict__ Cim,
    const float* __restrict__ logstep){
  __shared__ float4 spk01[Nst];
  __shared__ float4 spk23[Nst];
  __shared__ float2 slam [Nst];
  __shared__ float  s2step;
  int tid = threadIdx.x;
  int h = blockIdx.y;
  int l = blockIdx.x*256 + tid;
  if (tid < Nst){
    int i = h*Nst + tid;
    float pr = Pre[i], pi = Pim[i];
    float br = Bre[i], bi = Bim[i];
    float cr = Cre[i], ci = Cim[i];
    spk01[tid] = make_float4(cr*br + ci*bi, cr*bi - ci*br,
                             cr*pr + ci*pi, cr*pi - ci*pr);
    spk23[tid] = make_float4(pr*br + pi*bi, pr*bi - pi*br,
                             pr*pr + pi*pi, 0.f);
    slam [tid] = make_float2(fminf(Lre[i], -1e-4f), Lim[i]);
  }
  if (tid == 0) s2step = 2.f*expf(-logstep[h]);
  __syncthreads();
  float t   = tanf((float)(3.141592653589793/2048.0)*(float)l);
  float gim = s2step*t;
  float k00r=0.f,k00i=0.f,k01r=0.f,k01i=0.f,k10r=0.f,k10i=0.f,k11r=0.f,k11i=0.f;
  #pragma unroll 8
  for (int n = 0; n < Nst; n++){
    float2 lam = slam[n];
    float dre = -lam.x;
    float dim = gim - lam.y;
    float inv = frcp_fast(dre*dre + dim*dim);
    float ir  =  dre*inv;
    float ii  = -dim*inv;
    float4 w01 = spk01[n];
    float4 w23 = spk23[n];
    k00r += w01.x*ir - w01.y*ii;  k00i += w01.x*ii + w01.y*ir;
    k01r += w01.z*ir - w01.w*ii;  k01i += w01.z*ii + w01.w*ir;
    k10r += w23.x*ir - w23.y*ii;  k10i += w23.x*ii + w23.y*ir;
    k11r += w23.z*ir;             k11i += w23.z*ii;
  }
  float denr = 1.f + k11r, deni = k11i;
  float dinv = frcp_fast(denr*denr + deni*deni);
  float qr = denr*dinv, qi = -deni*dinv;
  float mr = k01r*k10r - k01i*k10i;
  float mi = k01r*k10i + k01i*k10r;
  float cr = mr*qr - mi*qi, ci2 = mr*qi + mi*qr;
  float ar = k00r - cr, ai = k00i - ci2;
  g_ar[(size_t)h*Lseq + l] = make_float2(ar - t*ai, ai + t*ar);
}

// ----------------- shared-mem radix-4 Stockham FFT(2048) ---------------------
template<bool INV>
__device__ __forceinline__ float2* fft2048_r4(float2* buf0, float2* buf1,
                                              const float2* stw, int tid){
  float2* src = buf0; float2* dst = buf1;
  #pragma unroll
  for (int st = 0; st < 5; st++){
    int s = 1 << (2*st);
    __syncthreads();
    #pragma unroll
    for (int i = 0; i < 2; i++){
      int idx = tid + 256*i;            // 0..511
      int sp  = idx & ~(s-1);
      float2 a0 = src[idx];
      float2 a1 = src[idx + 512];
      float2 a2 = src[idx + 1024];
      float2 a3 = src[idx + 1536];
      float2 w1 = stw[sp];
      float2 w2 = stw[2*sp];
      if (INV){ w1.y = -w1.y; w2.y = -w2.y; }
      float2 w3 = cmul(w1, w2);
      float2 t0 = cadd(a0, a2), t1 = csub(a0, a2);
      float2 t2 = cadd(a1, a3), t3 = csub(a1, a3);
      float2 b0 = cadd(t0, t2);
      float2 b2 = csub(t0, t2);
      float2 b1, b3;
      if (!INV){
        b1 = make_float2(t1.x + t3.y, t1.y - t3.x);   // t1 - i t3
        b3 = make_float2(t1.x - t3.y, t1.y + t3.x);   // t1 + i t3
      } else {
        b1 = make_float2(t1.x - t3.y, t1.y + t3.x);
        b3 = make_float2(t1.x + t3.y, t1.y - t3.x);
      }
      int j = idx + 3*sp;
      dst[j]       = b0;
      dst[j + s]   = cmul(b1, w1);
      dst[j + 2*s] = cmul(b2, w2);
      dst[j + 3*s] = cmul(b3, w3);
    }
    float2* tp = src; src = dst; dst = tp;
  }
  // final radix-2, s = 1024 (twiddle = 1)
  __syncthreads();
  #pragma unroll
  for (int i = 0; i < 4; i++){
    int idx = tid + 256*i;              // 0..1023
    float2 a = src[idx];
    float2 b = src[idx + 1024];
    dst[idx]        = cadd(a, b);
    dst[idx + 1024] = csub(a, b);
  }
  float2* tp = src; src = dst; dst = tp;
  __syncthreads();
  return src;
}

// ----------------- Kd kernel ------------------------------------------------
__global__ __launch_bounds__(256) void kd_kernel(float2* __restrict__ Kd){
  __shared__ float2 sA[2048];
  __shared__ float2 sB[2048];
  __shared__ float2 stw[1024];
  int tid = threadIdx.x;
  int h = blockIdx.x;
  for (int i = tid; i < 1024; i += 256) stw[i] = g_twA[i];
  const float2* ar = g_ar + (size_t)h*Lseq;
  #pragma unroll
  for (int i = 0; i < 8; i++){ int k = tid + 256*i; sA[k] = ar[k]; }
  float2* K = fft2048_r4<true>(sA, sB, stw, tid);
  float2* Ob = (K == sA) ? sB : sA;
  const float sc = 1.f/2048.f;
  #pragma unroll
  for (int i = 0; i < 8; i++){
    int n = tid + 256*i;
    float2 v = make_float2(0.f, 0.f);
    if (n < 1024) v = make_float2(K[2*n].x*sc, K[2*n+1].x*sc);
    Ob[n] = v;
  }
  float2* Zp = fft2048_r4<false>(Ob, K, stw, tid);
  float2* outKd = Kd + (size_t)h*2049;
  #pragma unroll
  for (int i = 0; i < 8; i++){
    int k  = tid + 256*i;
    int kc = (2048 - k) & 2047;
    float2 zk = Zp[k], zc = Zp[kc];
    float2 E  = make_float2(0.5f*(zk.x+zc.x),  0.5f*(zk.y-zc.y));
    float2 Od = make_float2(0.5f*(zk.y+zc.y), -0.5f*(zk.x-zc.x));
    outKd[k] = cadd(E, cmul(g_twB[k], Od));
  }
  if (tid == 0){
    float2 z0 = Zp[0];
    outKd[2048] = make_float2(z0.x - z0.y, 0.f);
  }
}

// ----------------- conv kernel ----------------------------------------------
__global__ __launch_bounds__(256) void conv_kernel(const float2* __restrict__ Kdbase){
  __shared__ float2 sA[2048];
  __shared__ float2 sB[2048];
  __shared__ float2 stw[1024];
  __shared__ float2 sY2048;
  int tid = threadIdx.x;
  int h = blockIdx.x;
  int b = blockIdx.y;
  const float* u = g_ht + ((size_t)b*Hdim + h)*Lseq;
  for (int i = tid; i < 1024; i += 256) stw[i] = g_twA[i];
  #pragma unroll
  for (int i = 0; i < 4; i++){
    int n = tid + 256*i;
    sA[n]        = make_float2(u[2*n], u[2*n+1]);
    sA[n + 1024] = make_float2(0.f, 0.f);
  }
  float2* Z = fft2048_r4<false>(sA, sB, stw, tid);
  float2* O = (Z == sA) ? sB : sA;
  const float2* kd = Kdbase + (size_t)h*2049;
  #pragma unroll
  for (int i = 0; i < 8; i++){
    int k  = tid + 256*i;
    int kc = (2048 - k) & 2047;
    float2 zk = Z[k], zc = Z[kc];
    float2 E  = make_float2(0.5f*(zk.x+zc.x),  0.5f*(zk.y-zc.y));
    float2 Od = make_float2(0.5f*(zk.y+zc.y), -0.5f*(zk.x-zc.x));
    float2 U  = cadd(E, cmul(g_twB[k], Od));
    O[k] = cmul(U, kd[k]);
  }
  if (tid == 0){
    float2 z0 = Z[0];
    float U2048 = z0.x - z0.y;
    float2 kv = kd[2048];
    sY2048 = make_float2(U2048*kv.x, U2048*kv.y);
  }
  __syncthreads();
  #pragma unroll
  for (int i = 0; i < 8; i++){
    int k = tid + 256*i;
    float2 Yk = O[k];
    float2 Yc = (k == 0) ? sY2048 : O[2048 - k];
    float2 Ey = make_float2(0.5f*(Yk.x+Yc.x), 0.5f*(Yk.y-Yc.y));
    float2 Dm = make_float2(0.5f*(Yk.x-Yc.x), 0.5f*(Yk.y+Yc.y));
    float2 tb = g_twB[k];
    float2 Oy = cmul(Dm, make_float2(tb.x, -tb.y));
    Z[k] = make_float2(Ey.x - Oy.y, Ey.y + Oy.x);
  }
  float2* w = fft2048_r4<true>(Z, O, stw, tid);
  float* out = g_yt + ((size_t)b*Hdim + h)*Lseq;
  const float sc = 1.f/2048.f;
  #pragma unroll
  for (int i = 0; i < 4; i++){
    int n = tid + 256*i;
    float2 v = w[n];
    out[2*n]   = v.x*sc;
    out[2*n+1] = v.y*sc;
  }
}

// ----------------- HMMA GEMM: 128x128 tile, bf16x3 compensation -------------
#define TROW    80
#define TBYTES  (128*TROW)
#define STAGEB  (4*TBYTES)
#define SMEM_GEMM (2*STAGEB)

__global__ __launch_bounds__(256) void hgemm_kernel(
    const __nv_bfloat16* __restrict__ A0g, const __nv_bfloat16* __restrict__ A1g,
    const __nv_bfloat16* __restrict__ B0g, const __nv_bfloat16* __restrict__ B1g,
    const float* __restrict__ bias, const float* __restrict__ aux,
    float* __restrict__ C, int mode,
    __nv_bfloat16* __restrict__ S0, __nv_bfloat16* __restrict__ S1)
{
  extern __shared__ char smem[];
  uint32_t sb = smem_u32(smem);
  int tid = threadIdx.x, wid = tid >> 5, lid = tid & 31;
  int bn = blockIdx.x*128, bm = blockIdx.y*128;
  int mw = wid & 3, nw = wid >> 2;

  int lrow = tid >> 1;
  int lc0  = tid & 1;

  int arow = lid & 15;
  int aoff = (lid >> 4) * 16;
  int brow = ((lid >> 4) << 3) + (lid & 7);
  int boff = ((lid >> 3) & 1) * 16;

  float acc[2][8][4];
  #pragma unroll
  for (int i = 0; i < 2; i++)
    #pragma unroll
    for (int j = 0; j < 8; j++)
      #pragma unroll
      for (int q = 0; q < 4; q++) acc[i][j][q] = 0.f;

  #pragma unroll
  for (int j = 0; j < 2; j++){
    int c = lc0 + 2*j;
    uint32_t so = (uint32_t)lrow*TROW + (uint32_t)c*16;
    size_t ga = (size_t)(bm + lrow)*Hdim + c*8;
    size_t gb = (size_t)(bn + lrow)*Hdim + c*8;
    cp16(sb + so,             A0g + ga);
    cp16(sb + TBYTES   + so,  A1g + ga);
    cp16(sb + 2*TBYTES + so,  B0g + gb);
    cp16(sb + 3*TBYTES + so,  B1g + gb);
  }
  CP_COMMIT();

  for (int ch = 0; ch < 16; ch++){
    int st = ch & 1;
    if (ch < 15){
      uint32_t sbase = sb + (st^1)*STAGEB;
      int k0 = (ch+1)*32;
      #pragma unroll
      for (int j = 0; j < 2; j++){
        int c = lc0 + 2*j;
        uint32_t so = (uint32_t)lrow*TROW + (uint32_t)c*16;
        size_t ga = (size_t)(bm + lrow)*Hdim + k0 + c*8;
        size_t gb = (size_t)(bn + lrow)*Hdim + k0 + c*8;
        cp16(sbase + so,             A0g + ga);
        cp16(sbase + TBYTES   + so,  A1g + ga);
        cp16(sbase + 2*TBYTES + so,  B0g + gb);
        cp16(sbase + 3*TBYTES + so,  B1g + gb);
      }
      CP_COMMIT();
      asm volatile("cp.async.wait_group 1;" ::: "memory");
    } else {
      asm volatile("cp.async.wait_group 0;" ::: "memory");
    }
    __syncthreads();

    uint32_t sA0 = sb + st*STAGEB;
    uint32_t sA1 = sA0 + TBYTES;
    uint32_t sB0 = sA0 + 2*TBYTES;
    uint32_t sB1 = sA0 + 3*TBYTES;
    #pragma unroll
    for (int ks = 0; ks < 2; ks++){
      int kb = ks*32;
      uint32_t a0f[2][4], a1f[2][4], b0f[4][4], b1f[4][4];
      #pragma unroll
      for (int mi = 0; mi < 2; mi++){
        uint32_t ro = (uint32_t)(mw*32 + mi*16 + arow)*TROW + kb + aoff;
        ldsm4(a0f[mi], sA0 + ro);
        ldsm4(a1f[mi], sA1 + ro);
      }
      #pragma unroll
      for (int nj = 0; nj < 4; nj++){
        uint32_t ro = (uint32_t)(nw*64 + nj*16 + brow)*TROW + kb + boff;
        ldsm4(b0f[nj], sB0 + ro);
        ldsm4(b1f[nj], sB1 + ro);
      }
      #pragma unroll
      for (int mi = 0; mi < 2; mi++){
        #pragma unroll
        for (int nt = 0; nt < 8; nt++){
          int nj = nt >> 1, sub = (nt & 1)*2;
          mma16816(acc[mi][nt], a0f[mi], &b0f[nj][sub]);
          mma16816(acc[mi][nt], a1f[mi], &b0f[nj][sub]);
          mma16816(acc[mi][nt], a0f[mi], &b1f[nj][sub]);
        }
      }
    }
    __syncthreads();
  }

  // epilogue
  int qr = lid >> 2, qc = (lid & 3)*2;
  #pragma unroll
  for (int mi = 0; mi < 2; mi++){
    #pragma unroll
    for (int hf = 0; hf < 2; hf++){
      int row = bm + mw*32 + mi*16 + hf*8 + qr;
      float* crow = C + (size_t)row*Hdim;
      const float* xrow = aux + (size_t)row*Hdim;
      #pragma unroll
      for (int nt = 0; nt < 8; nt++){
        int col = bn + nw*64 + nt*8 + qc;
        float2 bv = *(const float2*)(bias + col);
        float v0 = acc[mi][nt][hf*2+0] + bv.x;
        float v1 = acc[mi][nt][hf*2+1] + bv.y;
        float2 o;
        if (mode == 0){
          o = make_float2(v0, v1);
        } else if (mode == 1){
          o = make_float2(gelu_f(v0), gelu_f(v1));
        } else if (mode == 2){
          float2 cv = *(const float2*)(crow + col);
          float2 av = *(const float2*)(xrow + col);
          o.x = cv.x + av.x*sigm_f(v0);
          o.y = cv.y + av.y*sigm_f(v1);
        } else {
          float2 cv = *(const float2*)(crow + col);
          o = make_float2(cv.x + v0, cv.y + v1);
        }
        *(float2*)(crow + col) = o;
        if (S0){
          size_t gi = (size_t)row*Hdim + col;
          __nv_bfloat16 h0 = __float2bfloat16_rn(o.x);
          __nv_bfloat16 h1 = __float2bfloat16_rn(o.y);
          __nv_bfloat162 p; p.x = h0; p.y = h1;
          *(__nv_bfloat162*)(S0 + gi) = p;
          __nv_bfloat162 q;
          q.x = __float2bfloat16_rn(o.x - __bfloat162float(h0));
          q.y = __float2bfloat16_rn(o.y - __bfloat162float(h1));
          *(__nv_bfloat162*)(S1 + gi) = q;
        }
      }
    }
  }
}

// ----------------- host driver ----------------------------------------------
extern "C" void kernel_launch(void* const* d_in, const int* in_sizes, int n_in,
                              void* d_out, int out_size){
  (void)in_sizes; (void)n_in; (void)out_size;
  const float* x     = (const float*)d_in[0];
  const float* sLre  = (const float*)d_in[1];
  const float* sLim  = (const float*)d_in[2];
  const float* sPre  = (const float*)d_in[3];
  const float* sPim  = (const float*)d_in[4];
  const float* sBre  = (const float*)d_in[5];
  const float* sBim  = (const float*)d_in[6];
  const float* sCre  = (const float*)d_in[7];
  const float* sCim  = (const float*)d_in[8];
  const float* sD    = (const float*)d_in[9];
  const float* sLog  = (const float*)d_in[10];
  const float* sb_ls = (const float*)d_in[11];
  const float* sb_lb = (const float*)d_in[12];
  const float* sb_W1 = (const float*)d_in[13];
  const float* sb_b1 = (const float*)d_in[14];
  const float* sb_W2 = (const float*)d_in[15];
  const float* sb_b2 = (const float*)d_in[16];
  const float* bk_ls = (const float*)d_in[17];
  const float* bk_lb = (const float*)d_in[18];
  const float* bk_W1 = (const float*)d_in[19];
  const float* bk_b1 = (const float*)d_in[20];
  const float* bk_W2 = (const float*)d_in[21];
  const float* bk_b2 = (const float*)d_in[22];

  float *p_x, *p_z1;
  float2* p_kd;
  __nv_bfloat16 *p_a0, *p_a1, *p_b0, *p_b1, *p_wt0, *p_wt1;
  cudaGetSymbolAddress((void**)&p_x,   g_x);
  cudaGetSymbolAddress((void**)&p_z1,  g_z1);
  cudaGetSymbolAddress((void**)&p_kd,  g_KdL);
  cudaGetSymbolAddress((void**)&p_a0,  g_a0);
  cudaGetSymbolAddress((void**)&p_a1,  g_a1);
  cudaGetSymbolAddress((void**)&p_b0,  g_b0);
  cudaGetSymbolAddress((void**)&p_b1,  g_b1);
  cudaGetSymbolAddress((void**)&p_wt0, g_wt0);
  cudaGetSymbolAddress((void**)&p_wt1, g_wt1);

  cudaFuncSetAttribute(hgemm_kernel, cudaFuncAttributeMaxDynamicSharedMemorySize, SMEM_GEMM);

  // side stream + events (created at capture time only; replay runs no host code)
  cudaStream_t s2;
  cudaStreamCreateWithFlags(&s2, cudaStreamNonBlocking);
  cudaEvent_t evStart, evKd[4], evW[4], evWB[2];
  cudaEventCreateWithFlags(&evStart, cudaEventDisableTiming);
  for (int i = 0; i < 4; i++){
    cudaEventCreateWithFlags(&evKd[i], cudaEventDisableTiming);
    cudaEventCreateWithFlags(&evW[i],  cudaEventDisableTiming);
  }
  for (int b = 0; b < 2; b++) cudaEventCreateWithFlags(&evWB[b], cudaEventDisableTiming);

  dim3 wgrid(16, 16);
  dim3 tblk(32, 8);
  dim3 tgrid(Hdim/32, Lseq/32, Bsz);
  dim3 ggrid(Hdim/128, NROW/128);

  // main stream prologue
  init_tw_kernel<<<8, 256>>>();
  cudaMemcpyAsync(p_x, x, (size_t)BLH*sizeof(float), cudaMemcpyDeviceToDevice);
  cudaEventRecord(evStart, 0);

  // ---- side stream: SSM kernel chain + weight preps (independent of acts) ----
  cudaStreamWaitEvent(s2, evStart, 0);
  for (int i = 0; i < 4; i++){
    cauchy_kernel<<<dim3(Lseq/256, Hdim), 256, 0, s2>>>(
        sLre + i*HN, sLim + i*HN, sPre + i*HN, sPim + i*HN,
        sBre + i*HN, sBim + i*HN, sCre + i*HN, sCim + i*HN, sLog + i*Hdim);
    kd_kernel<<<Hdim, 256, 0, s2>>>(p_kd + (size_t)i*KDSZ);
    cudaEventRecord(evKd[i], s2);
    wprep_kernel<<<wgrid, tblk, 0, s2>>>(sb_W1 + (size_t)i*HH, i);
    wprep_kernel<<<wgrid, tblk, 0, s2>>>(sb_W2 + (size_t)i*HH, 4 + i);
    cudaEventRecord(evW[i], s2);
  }
  for (int b = 0; b < 2; b++){
    wprep_kernel<<<wgrid, tblk, 0, s2>>>(bk_W1 + (size_t)b*HH, 8 + b);
    wprep_kernel<<<wgrid, tblk, 0, s2>>>(bk_W2 + (size_t)b*HH, 10 + b);
    cudaEventRecord(evWB[b], s2);
  }

  // ---- main stream: activation chain ----
  for (int b = 0; b < 2; b++){
    for (int li = 0; li < 2; li++){
      int i = b*2 + li;
      ln_kernel<<<NROW/8, 256>>>(sb_ls + i*Hdim, sb_lb + i*Hdim, 0);
      transpose_fwd_kernel<<<tgrid, tblk>>>();
      cudaStreamWaitEvent(0, evKd[i], 0);
      conv_kernel<<<dim3(Hdim, Bsz), 256>>>(p_kd + (size_t)i*KDSZ);
      transpose_bwd_kernel<<<tgrid, tblk>>>(sD + i*Hdim);
      cudaStreamWaitEvent(0, evW[i], 0);
      hgemm_kernel<<<ggrid, 256, SMEM_GEMM>>>(p_a0, p_a1,
          p_wt0 + (size_t)i*HH, p_wt1 + (size_t)i*HH,
          sb_b1 + i*Hdim, p_z1, p_z1, 0, nullptr, nullptr);
      hgemm_kernel<<<ggrid, 256, SMEM_GEMM>>>(p_a0, p_a1,
          p_wt0 + (size_t)(4+i)*HH, p_wt1 + (size_t)(4+i)*HH,
          sb_b2 + i*Hdim, p_z1, p_x, 2, nullptr, nullptr);
    }
    ln_kernel<<<NROW/8, 256>>>(bk_ls + b*Hdim, bk_lb + b*Hdim, 1);
    cudaStreamWaitEvent(0, evWB[b], 0);
    hgemm_kernel<<<ggrid, 256, SMEM_GEMM>>>(p_a0, p_a1,
        p_wt0 + (size_t)(8+b)*HH, p_wt1 + (size_t)(8+b)*HH,
        bk_b1 + b*Hdim, p_z1, p_z1, 1, p_b0, p_b1);
    hgemm_kernel<<<ggrid, 256, SMEM_GEMM>>>(p_b0, p_b1,
        p_wt0 + (size_t)(10+b)*HH, p_wt1 + (size_t)(10+b)*HH,
        bk_b2 + b*Hdim, p_z1, p_x, 3, nullptr, nullptr);
  }
  cudaMemcpyAsync(d_out, p_x, (size_t)BLH*sizeof(float), cudaMemcpyDeviceToDevice);
}